// round 12
// baseline (speedup 1.0000x reference)
#include <cuda_runtime.h>
#include <cuda_fp16.h>
#include <math.h>
#include <stdint.h>

#define BSZ   8
#define C1    256
#define C2    256
#define CM    128
#define Hh    80
#define Ww    80
#define HW    6400
#define N9    9
#define KCN   1152      // CM * 9
#define NOFF  27
#define EPSF  1e-5f

// ---------------- scratch (device globals; no runtime alloc) ----------------
__device__ __align__(16) __half g_yh  [BSZ*HW*CM];    // NHWC y (fp16)
__device__ __align__(16) float  g_pred[BSZ*HW*NOFF];  // per-pixel [27] fp32
__device__ __align__(16) __half g_w1h [CM*C1];        // [o][k]
__device__ __align__(16) __half g_w2h [N9*32*CM];     // [n][o pad 32][c]
__device__ __align__(16) __half g_wdh [N9*CM*CM];     // [n][o][c]
__device__ __align__(16) __half g_w3h [C2*CM];        // [o][k]

__device__ __forceinline__ float silu_f(float v){ return v / (1.f + __expf(-v)); }
__device__ __forceinline__ uint32_t s2u(const void* p){
    return (uint32_t)__cvta_generic_to_shared(p);
}
__device__ __forceinline__ void cpa16(uint32_t s, const void* g){
    asm volatile("cp.async.cg.shared.global [%0], [%1], 16;" :: "r"(s), "l"(g));
}
#define CPA_COMMIT() asm volatile("cp.async.commit_group;" ::: "memory")
#define CPA_WAIT0()  asm volatile("cp.async.wait_group 0;" ::: "memory")

// row pitch in u32: 64 halves data (32 u32) + pad 4 -> 144B rows
#define HPAD 36

#define MMA_F16(accq, a0,a1,a2,a3, b0,b1) \
    asm volatile("mma.sync.aligned.m16n8k16.row.col.f32.f16.f16.f32 " \
        "{%0,%1,%2,%3}, {%4,%5,%6,%7}, {%8,%9}, {%0,%1,%2,%3};" \
        : "+f"((accq)[0]), "+f"((accq)[1]), "+f"((accq)[2]), "+f"((accq)[3]) \
        : "r"(a0), "r"(a1), "r"(a2), "r"(a3), "r"(b0), "r"(b1))

__device__ __forceinline__ void ldsm4(uint32_t* r, uint32_t a){
    asm volatile("ldmatrix.sync.aligned.m8n8.x4.shared.b16 {%0,%1,%2,%3}, [%4];"
        : "=r"(r[0]), "=r"(r[1]), "=r"(r[2]), "=r"(r[3]) : "r"(a));
}

// 128x128 warp-tiled fp16 mma, K-chunk = 64, ldmatrix fragment loads.
__device__ __forceinline__ void mma_f16_128_k64(uint32_t asu, uint32_t bsu,
        int wm, int wnn, int lane, float acc[2][8][4]){
    int l7 = lane & 7;
    uint32_t aBase = asu + (uint32_t)((wm*32 + ((lane>>3)&1)*8 + l7)*HPAD)*4 + (lane>>4)*16;
    uint32_t bBase = bsu + (uint32_t)((wnn*64 + ((lane>>4)&1)*8 + l7)*HPAD)*4 + ((lane>>3)&1)*16;
    #pragma unroll
    for (int kk = 0; kk < 4; kk++){
        uint32_t a[2][4];
        #pragma unroll
        for (int mt = 0; mt < 2; mt++)
            ldsm4(a[mt], aBase + (uint32_t)(mt*16*HPAD)*4 + kk*32);
        #pragma unroll
        for (int ntp = 0; ntp < 4; ntp++){
            uint32_t b[4];
            ldsm4(b, bBase + (uint32_t)(ntp*16*HPAD)*4 + kk*32);
            #pragma unroll
            for (int mt = 0; mt < 2; mt++){
                MMA_F16(acc[mt][2*ntp],   a[mt][0],a[mt][1],a[mt][2],a[mt][3], b[0],b[1]);
                MMA_F16(acc[mt][2*ntp+1], a[mt][0],a[mt][1],a[mt][2],a[mt][3], b[2],b[3]);
            }
        }
    }
}

// ---------------- K0: weight conversions/reshapes to fp16 ----------------
__global__ void prep_w(const float* __restrict__ w1, const float* __restrict__ w2,
                       const float* __restrict__ wd, const float* __restrict__ w3){
    int i = blockIdx.x*blockDim.x + threadIdx.x;
    if (i < CM*C1)  g_w1h[i] = __float2half(w1[i]);
    if (i < C2*CM)  g_w3h[i] = __float2half(w3[i]);
    if (i < N9*32*CM){
        int n = i/(32*CM); int o = (i/CM) & 31; int c = i % CM;
        g_w2h[i] = (o < NOFF) ? __float2half(w2[o*KCN + c*9 + n]) : __float2half(0.f);
    }
    if (i < N9*CM*CM){
        int n = i/(CM*CM); int rest = i%(CM*CM); int o = rest/CM, c = rest%CM;
        g_wdh[i] = __float2half(wd[o*KCN + c*9 + n]);
    }
}

// ---------------- K1: conv1x1(256->128) + bn1 + silu -> g_yh (NHWC fp16) ----------------
__global__ void __launch_bounds__(256, 2) k1_mma(const float* __restrict__ x,
        const float* __restrict__ g1, const float* __restrict__ b1,
        const float* __restrict__ m1, const float* __restrict__ v1){
    __shared__ __align__(16) uint32_t As[128*HPAD];
    __shared__ __align__(16) uint32_t Bs[128*HPAD];
    __shared__ float sS[128], sT[128];
    int blk = blockIdx.x;
    int b_ = blk / 50;
    int p0 = (blk % 50) * 128;
    int tid = threadIdx.x, warp = tid >> 5, lane = tid & 31;
    int wm = warp & 3, wnn = warp >> 2, gid = lane >> 2, tig = lane & 3;
    if (tid < 128){
        float s = g1[tid] * rsqrtf(v1[tid] + EPSF);
        sS[tid] = s;
        sT[tid] = b1[tid] - m1[tid]*s;
    }
    float acc[2][8][4] = {};
    const float* xb = x + (size_t)b_*C1*HW + p0;
    uint32_t asu = s2u(As), bsu = s2u(Bs);
    for (int kc = 0; kc < 4; kc++){
        int k0 = kc*64;
        // B: cp.async from pre-converted fp16 weights
        #pragma unroll
        for (int i = 0; i < 4; i++){
            int u = i*256 + tid; int r = u >> 3, seg = u & 7;
            cpa16(bsu + (r*HPAD + seg*4)*4, g_w1h + r*C1 + k0 + seg*8);
        }
        CPA_COMMIT();
        // A: direct NCHW fp32 load (coalesced over px), pack half2 along k
        #pragma unroll
        for (int i = 0; i < 16; i++){
            int e = i*256 + tid; int j = e >> 7, px = e & 127;
            float f0 = xb[(size_t)(k0 + 2*j)*HW + px];
            float f1 = xb[(size_t)(k0 + 2*j + 1)*HW + px];
            __half2 hh = __float22half2_rn(make_float2(f0, f1));
            As[px*HPAD + j] = *(uint32_t*)&hh;
        }
        CPA_WAIT0();
        __syncthreads();
        mma_f16_128_k64(asu, bsu, wm, wnn, lane, acc);
        __syncthreads();
    }
    #pragma unroll
    for (int mt = 0; mt < 2; mt++){
        int r0 = wm*32 + mt*16 + gid;
        __half2* z0 = (__half2*)(g_yh + (size_t)(b_*HW + p0 + r0)*CM);
        __half2* z1 = (__half2*)(g_yh + (size_t)(b_*HW + p0 + r0 + 8)*CM);
        #pragma unroll
        for (int nt = 0; nt < 8; nt++){
            int cb = wnn*64 + nt*8 + 2*tig;
            float s0 = sS[cb], s1 = sS[cb+1], t0 = sT[cb], t1 = sT[cb+1];
            z0[cb>>1] = __float22half2_rn(make_float2(
                silu_f(acc[mt][nt][0]*s0 + t0), silu_f(acc[mt][nt][1]*s1 + t1)));
            z1[cb>>1] = __float22half2_rn(make_float2(
                silu_f(acc[mt][nt][2]*s0 + t0), silu_f(acc[mt][nt][3]*s1 + t1)));
        }
    }
}

// ---------------- K2: conv3x3(128->27) via fp16 mma (implicit im2col) -> g_pred ----------------
__global__ void __launch_bounds__(256, 4) k2_mma(const float* __restrict__ offb){
    __shared__ __align__(16) uint32_t As[128*HPAD];
    __shared__ __align__(16) uint32_t Bs[32*HPAD];
    __shared__ float sB[32];
    int blk = blockIdx.x;
    int b_ = blk / 50;
    int p0 = (blk % 50) * 128;
    int tid = threadIdx.x, warp = tid >> 5, lane = tid & 31;
    int gid = lane >> 2, tig = lane & 3;
    int sub = lane >> 3, grp = lane & 7;     // 4 px x 8 channel-groups (8ch each)
    int l7 = lane & 7;
    if (tid < 32) sB[tid] = (tid < NOFF) ? offb[tid] : 0.f;
    uint32_t asu = s2u(As), bsu = s2u(Bs);
    uint32_t aBase = asu + (uint32_t)((warp*16 + ((lane>>3)&1)*8 + l7)*HPAD)*4 + (lane>>4)*16;
    uint32_t bBase = bsu + (uint32_t)((((lane>>4)&1)*8 + l7)*HPAD)*4 + ((lane>>3)&1)*16;

    float acc[4][4] = {};
    for (int it = 0; it < 18; it++){
        int n  = it >> 1;
        int c0 = (it & 1) << 6;
        int dy = n/3 - 1, dx = n%3 - 1;
        {
            int o = tid >> 3, seg = tid & 7;
            cpa16(bsu + (o*HPAD + seg*4)*4, g_w2h + (size_t)n*32*CM + o*CM + c0 + seg*8);
        }
        CPA_COMMIT();
        #pragma unroll
        for (int p = 0; p < 4; p++){
            int px = warp*16 + p*4 + sub;
            int pg = p0 + px, h = pg / Ww, w = pg % Ww;
            int sy = h + dy, sx = w + dx;
            bool ok = (sy >= 0) & (sy < Hh) & (sx >= 0) & (sx < Ww);
            uint4 t = make_uint4(0u,0u,0u,0u);
            if (ok)
                t = *(const uint4*)(g_yh + (size_t)(b_*HW + sy*Ww + sx)*CM + c0 + grp*8);
            *(uint4*)(As + px*HPAD + grp*4) = t;
        }
        CPA_WAIT0();
        __syncthreads();
        #pragma unroll
        for (int kk = 0; kk < 4; kk++){
            uint32_t a[4];
            ldsm4(a, aBase + kk*32);
            #pragma unroll
            for (int ntp = 0; ntp < 2; ntp++){
                uint32_t b[4];
                ldsm4(b, bBase + (uint32_t)(ntp*16*HPAD)*4 + kk*32);
                MMA_F16(acc[2*ntp],   a[0],a[1],a[2],a[3], b[0],b[1]);
                MMA_F16(acc[2*ntp+1], a[0],a[1],a[2],a[3], b[2],b[3]);
            }
        }
        __syncthreads();
    }
    #pragma unroll
    for (int half = 0; half < 2; half++){
        int px = warp*16 + gid + half*8;
        float* pp = g_pred + (size_t)(b_*HW + p0 + px)*NOFF;
        #pragma unroll
        for (int nt = 0; nt < 4; nt++){
            int c = nt*8 + 2*tig;
            float v0 = acc[nt][half*2 + 0] + sB[c];
            float v1 = acc[nt][half*2 + 1] + sB[c+1];
            if (c >= 18)   v0 = 1.f/(1.f + __expf(-v0));
            if (c+1 >= 18) v1 = 1.f/(1.f + __expf(-v1));
            if (c < NOFF)   pp[c]   = v0;
            if (c+1 < NOFF) pp[c+1] = v1;
        }
    }
}

// ---------------- K3: deform conv + bn2 + silu + conv1x1(128->256) + bn3 + silu + residual ----------------
#define K3_F_AS0  0
#define K3_F_AS1  (128*HPAD)
#define K3_F_BS0  (2*128*HPAD)
#define K3_F_BS1  (3*128*HPAD)
#define K3_F_IDX  (4*128*HPAD)
#define K3_F_WT   (K3_F_IDX + 4608)
#define K3_F_S    (K3_F_WT + 4608)
#define K3_F_T    (K3_F_S + 128)
#define K3_SMEM_F (K3_F_T + 128)

__global__ void __launch_bounds__(256, 2) k3_fused(const float* __restrict__ dcnb,
        const float* __restrict__ g2, const float* __restrict__ b2,
        const float* __restrict__ m2, const float* __restrict__ v2,
        const float* __restrict__ x, float* __restrict__ out,
        const float* __restrict__ g3, const float* __restrict__ b3,
        const float* __restrict__ m3, const float* __restrict__ v3){
    extern __shared__ float sm[];
    uint32_t* AsB[2] = { (uint32_t*)(sm + K3_F_AS0), (uint32_t*)(sm + K3_F_AS1) };
    int4*   sIdx = (int4*)(sm + K3_F_IDX);
    float4* sWt  = (float4*)(sm + K3_F_WT);
    float* sS = sm + K3_F_S;
    float* sT = sm + K3_F_T;

    int blk = blockIdx.x;
    int b_ = blk / 50;
    int p0 = (blk % 50) * 128;
    int tid = threadIdx.x, warp = tid >> 5, lane = tid & 31;

    // setup: precompute bilinear corner indices + mask/validity-folded weights
    for (int pr = tid; pr < 128*9; pr += 256){
        int p = pr / 9, nn = pr % 9;
        int pg = p0 + p, h = pg / Ww, w = pg % Ww;
        size_t pb = (size_t)(b_*HW + pg) * NOFF;
        float py = (float)(h - 1 + nn/3) + g_pred[pb + 2*nn];
        float qx = (float)(w - 1 + nn%3) + g_pred[pb + 2*nn + 1];
        float mk = g_pred[pb + 18 + nn];
        float y0f = floorf(py), x0f = floorf(qx);
        float wy = py - y0f, wx = qx - x0f;
        int iy0 = (int)y0f, ix0 = (int)x0f, iy1 = iy0 + 1, ix1 = ix0 + 1;
        float vy0 = (iy0 >= 0 && iy0 < Hh) ? 1.f : 0.f;
        float vy1 = (iy1 >= 0 && iy1 < Hh) ? 1.f : 0.f;
        float vx0 = (ix0 >= 0 && ix0 < Ww) ? 1.f : 0.f;
        float vx1 = (ix1 >= 0 && ix1 < Ww) ? 1.f : 0.f;
        int cy0 = min(max(iy0,0),Hh-1), cy1 = min(max(iy1,0),Hh-1);
        int cx0 = min(max(ix0,0),Ww-1), cx1 = min(max(ix1,0),Ww-1);
        int base = b_*HW;
        int4 id;
        id.x = (base + cy0*Ww + cx0)*CM;
        id.y = (base + cy0*Ww + cx1)*CM;
        id.z = (base + cy1*Ww + cx0)*CM;
        id.w = (base + cy1*Ww + cx1)*CM;
        float4 wt;
        wt.x = (1.f-wy)*(1.f-wx)*mk*vy0*vx0;
        wt.y = (1.f-wy)*wx      *mk*vy0*vx1;
        wt.z = wy*(1.f-wx)      *mk*vy1*vx0;
        wt.w = wy*wx            *mk*vy1*vx1;
        sIdx[pr] = id;
        sWt[pr]  = wt;
    }
    if (tid < 128){
        float s = g2[tid] * rsqrtf(v2[tid] + EPSF);
        sS[tid] = s;
        sT[tid] = dcnb[tid]*s + b2[tid] - m2[tid]*s;
    }
    __syncthreads();

    int wm = warp & 3, wnn = warp >> 2, gid = lane >> 2, tig = lane & 3;
    int sub = lane >> 3, grp = lane & 7;   // 4 px x 8 channel-groups (8ch each)
    float acc[2][8][4] = {};
    uint32_t asuB[2] = { s2u(AsB[0]), s2u(AsB[1]) };
    uint32_t bsuB[2] = { s2u((uint32_t*)(sm + K3_F_BS0)), s2u((uint32_t*)(sm + K3_F_BS1)) };

    auto fillB = [&](int it, int buf){
        int n = it >> 1, c0 = (it & 1) << 6;
        const __half* wn = g_wdh + (size_t)n*(CM*CM) + c0;
        uint32_t bu = bsuB[buf];
        #pragma unroll
        for (int i = 0; i < 4; i++){
            int u = i*256 + tid; int o = u >> 3, seg = u & 7;
            cpa16(bu + (o*HPAD + seg*4)*4, wn + o*CM + seg*8);
        }
    };
    auto fillA = [&](int it, int buf){
        int n = it >> 1, c0 = (it & 1) << 6;
        const __half* yb = g_yh + c0 + grp*8;
        uint32_t* Ad = AsB[buf];
        #pragma unroll
        for (int p = 0; p < 4; p++){
            int px = warp*16 + p*4 + sub;
            int pr = px*9 + n;
            int4   id = sIdx[pr];
            float4 wt = sWt[pr];
            uint4 c00 = *(const uint4*)(yb + id.x);
            uint4 c01 = *(const uint4*)(yb + id.y);
            uint4 c10 = *(const uint4*)(yb + id.z);
            uint4 c11 = *(const uint4*)(yb + id.w);
            uint4 t;
            #pragma unroll
            for (int q = 0; q < 4; q++){
                float2 f0 = __half22float2(((__half2*)&c00)[q]);
                float2 f1 = __half22float2(((__half2*)&c01)[q]);
                float2 f2 = __half22float2(((__half2*)&c10)[q]);
                float2 f3 = __half22float2(((__half2*)&c11)[q]);
                float2 v;
                v.x = wt.x*f0.x + wt.y*f1.x + wt.z*f2.x + wt.w*f3.x;
                v.y = wt.x*f0.y + wt.y*f1.y + wt.z*f2.y + wt.w*f3.y;
                ((__half2*)&t)[q] = __float22half2_rn(v);
            }
            *(uint4*)(Ad + px*HPAD + grp*4) = t;
        }
    };

    // prologue
    fillB(0, 0); CPA_COMMIT();
    fillA(0, 0);
    CPA_WAIT0();
    __syncthreads();

    int cur = 0;
    for (int it = 0; it < 18; it++){
        int nb = cur ^ 1;
        if (it < 17){ fillB(it+1, nb); CPA_COMMIT(); }
        mma_f16_128_k64(asuB[cur], bsuB[cur], wm, wnn, lane, acc);
        if (it < 17) fillA(it+1, nb);
        CPA_WAIT0();
        __syncthreads();
        cur = nb;
    }

    // ---- stage 2: bn2+silu -> z tile (fp16) into As buffers [128px][128ch] ----
    // buffer = channel>>6; conflict-free store (banks 4*gid+tig distinct).
    #pragma unroll
    for (int mt = 0; mt < 2; mt++){
        int r0 = wm*32 + mt*16 + gid;
        uint32_t* Az = AsB[wnn];
        #pragma unroll
        for (int nt = 0; nt < 8; nt++){
            int cb = wnn*64 + nt*8 + 2*tig;     // global ch
            int lc = (cb & 63) >> 1;            // u32 col in buffer
            float s0 = sS[cb], s1 = sS[cb+1], t0 = sT[cb], t1 = sT[cb+1];
            __half2 h0 = __float22half2_rn(make_float2(
                silu_f(acc[mt][nt][0]*s0 + t0), silu_f(acc[mt][nt][1]*s1 + t1)));
            __half2 h1 = __float22half2_rn(make_float2(
                silu_f(acc[mt][nt][2]*s0 + t0), silu_f(acc[mt][nt][3]*s1 + t1)));
            Az[(r0)*HPAD + lc]     = *(uint32_t*)&h0;
            Az[(r0+8)*HPAD + lc]   = *(uint32_t*)&h1;
        }
    }
    // bn3 params into dead sIdx region
    float* sS3 = (float*)sIdx;
    float* sT3 = sS3 + 256;
    {
        int o = tid;
        float s = g3[o] * rsqrtf(v3[o] + EPSF);
        sS3[o] = s;
        sT3[o] = b3[o] - m3[o]*s;
    }
    __syncthreads();

    // ---- stage 3: conv1x1 128->256 on z tile, + bn3 + silu + residual -> out ----
    for (int og = 0; og < 2; og++){
        float acc2[2][8][4] = {};
        for (int kc = 0; kc < 2; kc++){
            const __half* wb = g_w3h + (size_t)(og*128)*CM + kc*64;
            #pragma unroll
            for (int i = 0; i < 4; i++){
                int u = i*256 + tid; int o = u >> 3, seg = u & 7;
                cpa16(bsuB[0] + (o*HPAD + seg*4)*4, wb + o*CM + seg*8);
            }
            CPA_COMMIT();
            CPA_WAIT0();
            __syncthreads();
            mma_f16_128_k64(asuB[kc], bsuB[0], wm, wnn, lane, acc2);
            __syncthreads();
        }
        #pragma unroll
        for (int mt = 0; mt < 2; mt++){
            int pg0 = p0 + wm*32 + mt*16 + gid;
            #pragma unroll
            for (int nt = 0; nt < 8; nt++){
                int ol = wnn*64 + nt*8 + 2*tig;
                int o = og*128 + ol;
                float s0 = sS3[o], s1 = sS3[o+1];
                float t0 = sT3[o], t1 = sT3[o+1];
                size_t i00 = ((size_t)b_*C2 + o)*HW + pg0;
                size_t i01 = i00 + HW;
                out[i00]     = x[i00]     + silu_f(acc2[mt][nt][0]*s0 + t0);
                out[i01]     = x[i01]     + silu_f(acc2[mt][nt][1]*s1 + t1);
                out[i00 + 8] = x[i00 + 8] + silu_f(acc2[mt][nt][2]*s0 + t0);
                out[i01 + 8] = x[i01 + 8] + silu_f(acc2[mt][nt][3]*s1 + t1);
            }
        }
    }
}

// ---------------- launch ----------------
extern "C" void kernel_launch(void* const* d_in, const int* in_sizes, int n_in,
                              void* d_out, int out_size){
    const float* x     = (const float*)d_in[0];
    const float* cv1_w = (const float*)d_in[1];
    const float* bn1g  = (const float*)d_in[2];
    const float* bn1b  = (const float*)d_in[3];
    const float* bn1m  = (const float*)d_in[4];
    const float* bn1v  = (const float*)d_in[5];
    const float* off_w = (const float*)d_in[6];
    const float* off_b = (const float*)d_in[7];
    const float* dcn_w = (const float*)d_in[8];
    const float* dcn_b = (const float*)d_in[9];
    const float* bn2g  = (const float*)d_in[10];
    const float* bn2b  = (const float*)d_in[11];
    const float* bn2m  = (const float*)d_in[12];
    const float* bn2v  = (const float*)d_in[13];
    const float* cv3_w = (const float*)d_in[14];
    const float* bn3g  = (const float*)d_in[15];
    const float* bn3b  = (const float*)d_in[16];
    const float* bn3m  = (const float*)d_in[17];
    const float* bn3v  = (const float*)d_in[18];
    float* out = (float*)d_out;

    prep_w<<<(N9*CM*CM + 255)/256, 256>>>(cv1_w, off_w, dcn_w, cv3_w);
    k1_mma<<<BSZ*50, 256>>>(x, bn1g, bn1b, bn1m, bn1v);
    k2_mma<<<BSZ*50, 256>>>(off_b);

    int smem_bytes = K3_SMEM_F * 4;  // 111616 B
    cudaFuncSetAttribute(k3_fused, cudaFuncAttributeMaxDynamicSharedMemorySize, smem_bytes);
    k3_fused<<<BSZ*50, 256, smem_bytes>>>(dcn_b, bn2g, bn2b, bn2m, bn2v,
                                          x, out, bn3g, bn3b, bn3m, bn3v);
}

// round 13
// speedup vs baseline: 1.0290x; 1.0290x over previous
#include <cuda_runtime.h>
#include <cuda_fp16.h>
#include <math.h>
#include <stdint.h>

#define BSZ   8
#define C1    256
#define C2    256
#define CM    128
#define Hh    80
#define Ww    80
#define HW    6400
#define N9    9
#define KCN   1152      // CM * 9
#define NOFF  27
#define EPSF  1e-5f

// ---------------- scratch (device globals; no runtime alloc) ----------------
__device__ __align__(16) __half g_yh  [BSZ*HW*CM];    // NHWC y (fp16)
__device__ __align__(16) __half g_zh  [BSZ*HW*CM];    // NHWC z (fp16)
__device__ __align__(16) float  g_pred[BSZ*HW*NOFF];  // per-pixel [27] fp32
__device__ __align__(16) __half g_w1h [CM*C1];        // [o][k]
__device__ __align__(16) __half g_w2h [N9*32*CM];     // [n][o pad 32][c]
__device__ __align__(16) __half g_wdh [N9*CM*CM];     // [n][o][c]
__device__ __align__(16) __half g_w3h [C2*CM];        // [o][k]

__device__ __forceinline__ float silu_f(float v){ return v / (1.f + __expf(-v)); }
__device__ __forceinline__ uint32_t s2u(const void* p){
    return (uint32_t)__cvta_generic_to_shared(p);
}
__device__ __forceinline__ void cpa16(uint32_t s, const void* g){
    asm volatile("cp.async.cg.shared.global [%0], [%1], 16;" :: "r"(s), "l"(g));
}
#define CPA_COMMIT() asm volatile("cp.async.commit_group;" ::: "memory")
#define CPA_WAIT0()  asm volatile("cp.async.wait_group 0;" ::: "memory")

// row pitch in u32: 64 halves data (32 u32) + pad 4 -> 144B rows
#define HPAD 36

#define MMA_F16(accq, a0,a1,a2,a3, b0,b1) \
    asm volatile("mma.sync.aligned.m16n8k16.row.col.f32.f16.f16.f32 " \
        "{%0,%1,%2,%3}, {%4,%5,%6,%7}, {%8,%9}, {%0,%1,%2,%3};" \
        : "+f"((accq)[0]), "+f"((accq)[1]), "+f"((accq)[2]), "+f"((accq)[3]) \
        : "r"(a0), "r"(a1), "r"(a2), "r"(a3), "r"(b0), "r"(b1))

__device__ __forceinline__ void ldsm4(uint32_t* r, uint32_t a){
    asm volatile("ldmatrix.sync.aligned.m8n8.x4.shared.b16 {%0,%1,%2,%3}, [%4];"
        : "=r"(r[0]), "=r"(r[1]), "=r"(r[2]), "=r"(r[3]) : "r"(a));
}

// 128x128 warp-tiled fp16 mma, K-chunk = 64, ldmatrix fragment loads.
__device__ __forceinline__ void mma_f16_128_k64(uint32_t asu, uint32_t bsu,
        int wm, int wnn, int lane, float acc[2][8][4]){
    int l7 = lane & 7;
    uint32_t aBase = asu + (uint32_t)((wm*32 + ((lane>>3)&1)*8 + l7)*HPAD)*4 + (lane>>4)*16;
    uint32_t bBase = bsu + (uint32_t)((wnn*64 + ((lane>>4)&1)*8 + l7)*HPAD)*4 + ((lane>>3)&1)*16;
    #pragma unroll
    for (int kk = 0; kk < 4; kk++){
        uint32_t a[2][4];
        #pragma unroll
        for (int mt = 0; mt < 2; mt++)
            ldsm4(a[mt], aBase + (uint32_t)(mt*16*HPAD)*4 + kk*32);
        #pragma unroll
        for (int ntp = 0; ntp < 4; ntp++){
            uint32_t b[4];
            ldsm4(b, bBase + (uint32_t)(ntp*16*HPAD)*4 + kk*32);
            #pragma unroll
            for (int mt = 0; mt < 2; mt++){
                MMA_F16(acc[mt][2*ntp],   a[mt][0],a[mt][1],a[mt][2],a[mt][3], b[0],b[1]);
                MMA_F16(acc[mt][2*ntp+1], a[mt][0],a[mt][1],a[mt][2],a[mt][3], b[2],b[3]);
            }
        }
    }
}

// ---------------- K0: weight conversions/reshapes to fp16 ----------------
__global__ void prep_w(const float* __restrict__ w1, const float* __restrict__ w2,
                       const float* __restrict__ wd, const float* __restrict__ w3){
    int i = blockIdx.x*blockDim.x + threadIdx.x;
    if (i < CM*C1)  g_w1h[i] = __float2half(w1[i]);
    if (i < C2*CM)  g_w3h[i] = __float2half(w3[i]);
    if (i < N9*32*CM){
        int n = i/(32*CM); int o = (i/CM) & 31; int c = i % CM;
        g_w2h[i] = (o < NOFF) ? __float2half(w2[o*KCN + c*9 + n]) : __float2half(0.f);
    }
    if (i < N9*CM*CM){
        int n = i/(CM*CM); int rest = i%(CM*CM); int o = rest/CM, c = rest%CM;
        g_wdh[i] = __float2half(wd[o*KCN + c*9 + n]);
    }
}

// ---------------- K1: conv1x1(256->128) + bn1 + silu -> g_yh (NHWC fp16), direct NCHW A ----------------
__global__ void __launch_bounds__(256, 2) k1_mma(const float* __restrict__ x,
        const float* __restrict__ g1, const float* __restrict__ b1,
        const float* __restrict__ m1, const float* __restrict__ v1){
    __shared__ __align__(16) uint32_t As[128*HPAD];
    __shared__ __align__(16) uint32_t Bs[128*HPAD];
    __shared__ float sS[128], sT[128];
    int blk = blockIdx.x;
    int b_ = blk / 50;
    int p0 = (blk % 50) * 128;
    int tid = threadIdx.x, warp = tid >> 5, lane = tid & 31;
    int wm = warp & 3, wnn = warp >> 2, gid = lane >> 2, tig = lane & 3;
    if (tid < 128){
        float s = g1[tid] * rsqrtf(v1[tid] + EPSF);
        sS[tid] = s;
        sT[tid] = b1[tid] - m1[tid]*s;
    }
    float acc[2][8][4] = {};
    const float* xb = x + (size_t)b_*C1*HW + p0;
    uint32_t asu = s2u(As), bsu = s2u(Bs);
    for (int kc = 0; kc < 4; kc++){
        int k0 = kc*64;
        // B: cp.async from pre-converted fp16 weights
        #pragma unroll
        for (int i = 0; i < 4; i++){
            int u = i*256 + tid; int r = u >> 3, seg = u & 7;
            cpa16(bsu + (r*HPAD + seg*4)*4, g_w1h + r*C1 + k0 + seg*8);
        }
        CPA_COMMIT();
        // A: direct NCHW fp32 load (coalesced over px), pack half2 along k
        #pragma unroll
        for (int i = 0; i < 16; i++){
            int e = i*256 + tid; int j = e >> 7, px = e & 127;
            float f0 = xb[(size_t)(k0 + 2*j)*HW + px];
            float f1 = xb[(size_t)(k0 + 2*j + 1)*HW + px];
            __half2 hh = __float22half2_rn(make_float2(f0, f1));
            As[px*HPAD + j] = *(uint32_t*)&hh;
        }
        CPA_WAIT0();
        __syncthreads();
        mma_f16_128_k64(asu, bsu, wm, wnn, lane, acc);
        __syncthreads();
    }
    #pragma unroll
    for (int mt = 0; mt < 2; mt++){
        int r0 = wm*32 + mt*16 + gid;
        __half2* z0 = (__half2*)(g_yh + (size_t)(b_*HW + p0 + r0)*CM);
        __half2* z1 = (__half2*)(g_yh + (size_t)(b_*HW + p0 + r0 + 8)*CM);
        #pragma unroll
        for (int nt = 0; nt < 8; nt++){
            int cb = wnn*64 + nt*8 + 2*tig;
            float s0 = sS[cb], s1 = sS[cb+1], t0 = sT[cb], t1 = sT[cb+1];
            z0[cb>>1] = __float22half2_rn(make_float2(
                silu_f(acc[mt][nt][0]*s0 + t0), silu_f(acc[mt][nt][1]*s1 + t1)));
            z1[cb>>1] = __float22half2_rn(make_float2(
                silu_f(acc[mt][nt][2]*s0 + t0), silu_f(acc[mt][nt][3]*s1 + t1)));
        }
    }
}

// ---------------- K2: conv3x3(128->27) via fp16 mma (implicit im2col) -> g_pred ----------------
__global__ void __launch_bounds__(256, 4) k2_mma(const float* __restrict__ offb){
    __shared__ __align__(16) uint32_t As[128*HPAD];
    __shared__ __align__(16) uint32_t Bs[32*HPAD];
    __shared__ float sB[32];
    int blk = blockIdx.x;
    int b_ = blk / 50;
    int p0 = (blk % 50) * 128;
    int tid = threadIdx.x, warp = tid >> 5, lane = tid & 31;
    int gid = lane >> 2, tig = lane & 3;
    int sub = lane >> 3, grp = lane & 7;     // 4 px x 8 channel-groups (8ch each)
    int l7 = lane & 7;
    if (tid < 32) sB[tid] = (tid < NOFF) ? offb[tid] : 0.f;
    uint32_t asu = s2u(As), bsu = s2u(Bs);
    uint32_t aBase = asu + (uint32_t)((warp*16 + ((lane>>3)&1)*8 + l7)*HPAD)*4 + (lane>>4)*16;
    uint32_t bBase = bsu + (uint32_t)((((lane>>4)&1)*8 + l7)*HPAD)*4 + ((lane>>3)&1)*16;

    float acc[4][4] = {};
    for (int it = 0; it < 18; it++){
        int n  = it >> 1;
        int c0 = (it & 1) << 6;
        int dy = n/3 - 1, dx = n%3 - 1;
        {
            int o = tid >> 3, seg = tid & 7;
            cpa16(bsu + (o*HPAD + seg*4)*4, g_w2h + (size_t)n*32*CM + o*CM + c0 + seg*8);
        }
        CPA_COMMIT();
        #pragma unroll
        for (int p = 0; p < 4; p++){
            int px = warp*16 + p*4 + sub;
            int pg = p0 + px, h = pg / Ww, w = pg % Ww;
            int sy = h + dy, sx = w + dx;
            bool ok = (sy >= 0) & (sy < Hh) & (sx >= 0) & (sx < Ww);
            uint4 t = make_uint4(0u,0u,0u,0u);
            if (ok)
                t = *(const uint4*)(g_yh + (size_t)(b_*HW + sy*Ww + sx)*CM + c0 + grp*8);
            *(uint4*)(As + px*HPAD + grp*4) = t;
        }
        CPA_WAIT0();
        __syncthreads();
        #pragma unroll
        for (int kk = 0; kk < 4; kk++){
            uint32_t a[4];
            ldsm4(a, aBase + kk*32);
            #pragma unroll
            for (int ntp = 0; ntp < 2; ntp++){
                uint32_t b[4];
                ldsm4(b, bBase + (uint32_t)(ntp*16*HPAD)*4 + kk*32);
                MMA_F16(acc[2*ntp],   a[0],a[1],a[2],a[3], b[0],b[1]);
                MMA_F16(acc[2*ntp+1], a[0],a[1],a[2],a[3], b[2],b[3]);
            }
        }
        __syncthreads();
    }
    #pragma unroll
    for (int half = 0; half < 2; half++){
        int px = warp*16 + gid + half*8;
        float* pp = g_pred + (size_t)(b_*HW + p0 + px)*NOFF;
        #pragma unroll
        for (int nt = 0; nt < 4; nt++){
            int c = nt*8 + 2*tig;
            float v0 = acc[nt][half*2 + 0] + sB[c];
            float v1 = acc[nt][half*2 + 1] + sB[c+1];
            if (c >= 18)   v0 = 1.f/(1.f + __expf(-v0));
            if (c+1 >= 18) v1 = 1.f/(1.f + __expf(-v1));
            if (c < NOFF)   pp[c]   = v0;
            if (c+1 < NOFF) pp[c+1] = v1;
        }
    }
}

// ---------------- K3: deform conv via fp16 mma, K-chunk 64, double-buffered ----------------
#define K3_F_AS0  0
#define K3_F_AS1  (128*HPAD)
#define K3_F_BS0  (2*128*HPAD)
#define K3_F_BS1  (3*128*HPAD)
#define K3_F_IDX  (4*128*HPAD)
#define K3_F_WT   (K3_F_IDX + 4608)
#define K3_F_S    (K3_F_WT + 4608)
#define K3_F_T    (K3_F_S + 128)
#define K3_SMEM_F (K3_F_T + 128)

__global__ void __launch_bounds__(256, 2) k3_deform_mma(const float* __restrict__ dcnb,
        const float* __restrict__ g2, const float* __restrict__ b2,
        const float* __restrict__ m2, const float* __restrict__ v2){
    extern __shared__ float sm[];
    uint32_t* AsB[2] = { (uint32_t*)(sm + K3_F_AS0), (uint32_t*)(sm + K3_F_AS1) };
    int4*   sIdx = (int4*)(sm + K3_F_IDX);
    float4* sWt  = (float4*)(sm + K3_F_WT);
    float* sS = sm + K3_F_S;
    float* sT = sm + K3_F_T;

    int blk = blockIdx.x;
    int b_ = blk / 50;
    int p0 = (blk % 50) * 128;
    int tid = threadIdx.x, warp = tid >> 5, lane = tid & 31;

    // setup: precompute bilinear corner indices + mask/validity-folded weights
    for (int pr = tid; pr < 128*9; pr += 256){
        int p = pr / 9, nn = pr % 9;
        int pg = p0 + p, h = pg / Ww, w = pg % Ww;
        size_t pb = (size_t)(b_*HW + pg) * NOFF;
        float py = (float)(h - 1 + nn/3) + g_pred[pb + 2*nn];
        float qx = (float)(w - 1 + nn%3) + g_pred[pb + 2*nn + 1];
        float mk = g_pred[pb + 18 + nn];
        float y0f = floorf(py), x0f = floorf(qx);
        float wy = py - y0f, wx = qx - x0f;
        int iy0 = (int)y0f, ix0 = (int)x0f, iy1 = iy0 + 1, ix1 = ix0 + 1;
        float vy0 = (iy0 >= 0 && iy0 < Hh) ? 1.f : 0.f;
        float vy1 = (iy1 >= 0 && iy1 < Hh) ? 1.f : 0.f;
        float vx0 = (ix0 >= 0 && ix0 < Ww) ? 1.f : 0.f;
        float vx1 = (ix1 >= 0 && ix1 < Ww) ? 1.f : 0.f;
        int cy0 = min(max(iy0,0),Hh-1), cy1 = min(max(iy1,0),Hh-1);
        int cx0 = min(max(ix0,0),Ww-1), cx1 = min(max(ix1,0),Ww-1);
        int base = b_*HW;
        int4 id;
        id.x = (base + cy0*Ww + cx0)*CM;
        id.y = (base + cy0*Ww + cx1)*CM;
        id.z = (base + cy1*Ww + cx0)*CM;
        id.w = (base + cy1*Ww + cx1)*CM;
        float4 wt;
        wt.x = (1.f-wy)*(1.f-wx)*mk*vy0*vx0;
        wt.y = (1.f-wy)*wx      *mk*vy0*vx1;
        wt.z = wy*(1.f-wx)      *mk*vy1*vx0;
        wt.w = wy*wx            *mk*vy1*vx1;
        sIdx[pr] = id;
        sWt[pr]  = wt;
    }
    if (tid < 128){
        float s = g2[tid] * rsqrtf(v2[tid] + EPSF);
        sS[tid] = s;
        sT[tid] = dcnb[tid]*s + b2[tid] - m2[tid]*s;
    }
    __syncthreads();

    int wm = warp & 3, wnn = warp >> 2, gid = lane >> 2, tig = lane & 3;
    int sub = lane >> 3, grp = lane & 7;   // 4 px x 8 channel-groups (8ch each)
    float acc[2][8][4] = {};
    uint32_t asuB[2] = { s2u(AsB[0]), s2u(AsB[1]) };
    uint32_t bsuB[2] = { s2u((uint32_t*)(sm + K3_F_BS0)), s2u((uint32_t*)(sm + K3_F_BS1)) };

    auto fillB = [&](int it, int buf){
        int n = it >> 1, c0 = (it & 1) << 6;
        const __half* wn = g_wdh + (size_t)n*(CM*CM) + c0;
        uint32_t bu = bsuB[buf];
        #pragma unroll
        for (int i = 0; i < 4; i++){
            int u = i*256 + tid; int o = u >> 3, seg = u & 7;
            cpa16(bu + (o*HPAD + seg*4)*4, wn + o*CM + seg*8);
        }
    };
    auto fillA = [&](int it, int buf){
        int n = it >> 1, c0 = (it & 1) << 6;
        const __half* yb = g_yh + c0 + grp*8;
        uint32_t* Ad = AsB[buf];
        #pragma unroll
        for (int p = 0; p < 4; p++){
            int px = warp*16 + p*4 + sub;
            int pr = px*9 + n;
            int4   id = sIdx[pr];
            float4 wt = sWt[pr];
            uint4 c00 = *(const uint4*)(yb + id.x);
            uint4 c01 = *(const uint4*)(yb + id.y);
            uint4 c10 = *(const uint4*)(yb + id.z);
            uint4 c11 = *(const uint4*)(yb + id.w);
            uint4 t;
            #pragma unroll
            for (int q = 0; q < 4; q++){
                float2 f0 = __half22float2(((__half2*)&c00)[q]);
                float2 f1 = __half22float2(((__half2*)&c01)[q]);
                float2 f2 = __half22float2(((__half2*)&c10)[q]);
                float2 f3 = __half22float2(((__half2*)&c11)[q]);
                float2 v;
                v.x = wt.x*f0.x + wt.y*f1.x + wt.z*f2.x + wt.w*f3.x;
                v.y = wt.x*f0.y + wt.y*f1.y + wt.z*f2.y + wt.w*f3.y;
                ((__half2*)&t)[q] = __float22half2_rn(v);
            }
            *(uint4*)(Ad + px*HPAD + grp*4) = t;
        }
    };

    // prologue
    fillB(0, 0); CPA_COMMIT();
    fillA(0, 0);
    CPA_WAIT0();
    __syncthreads();

    int cur = 0;
    for (int it = 0; it < 18; it++){
        int nb = cur ^ 1;
        if (it < 17){ fillB(it+1, nb); CPA_COMMIT(); }
        mma_f16_128_k64(asuB[cur], bsuB[cur], wm, wnn, lane, acc);
        if (it < 17) fillA(it+1, nb);
        CPA_WAIT0();
        __syncthreads();
        cur = nb;
    }

    // epilogue: bn2 + silu -> g_zh (fp16 NHWC)
    #pragma unroll
    for (int mt = 0; mt < 2; mt++){
        int r0 = wm*32 + mt*16 + gid;
        __half2* z0 = (__half2*)(g_zh + (size_t)(b_*HW + p0 + r0)*CM);
        __half2* z1 = (__half2*)(g_zh + (size_t)(b_*HW + p0 + r0 + 8)*CM);
        #pragma unroll
        for (int nt = 0; nt < 8; nt++){
            int cb = wnn*64 + nt*8 + 2*tig;
            float s0 = sS[cb], s1 = sS[cb+1], t0 = sT[cb], t1 = sT[cb+1];
            z0[cb>>1] = __float22half2_rn(make_float2(
                silu_f(acc[mt][nt][0]*s0 + t0), silu_f(acc[mt][nt][1]*s1 + t1)));
            z1[cb>>1] = __float22half2_rn(make_float2(
                silu_f(acc[mt][nt][2]*s0 + t0), silu_f(acc[mt][nt][3]*s1 + t1)));
        }
    }
}

// ---------------- K4: conv1x1(128->256) + bn3 + silu + residual -> out (NCHW) ----------------
__global__ void __launch_bounds__(256, 2) k4_mma(const float* __restrict__ x, float* __restrict__ out,
        const float* __restrict__ g3, const float* __restrict__ b3,
        const float* __restrict__ m3, const float* __restrict__ v3){
    __shared__ __align__(16) uint32_t As[128*HPAD];
    __shared__ __align__(16) uint32_t Bs[128*HPAD];
    __shared__ float sS[128], sT[128];
    int blk = blockIdx.x;
    int b_ = blk / 50;
    int p0 = (blk % 50) * 128;
    int o0g = blockIdx.y * 128;
    int tid = threadIdx.x, warp = tid >> 5, lane = tid & 31;
    int wm = warp & 3, wnn = warp >> 2, gid = lane >> 2, tig = lane & 3;
    if (tid < 128){
        int o = o0g + tid;
        float s = g3[o] * rsqrtf(v3[o] + EPSF);
        sS[tid] = s;
        sT[tid] = b3[o] - m3[o]*s;
    }
    float acc[2][8][4] = {};
    const __half* zt = g_zh + (size_t)(b_*HW + p0)*CM;
    const __half* wb = g_w3h + (size_t)o0g*CM;
    uint32_t asu = s2u(As), bsu = s2u(Bs);
    for (int kc = 0; kc < 2; kc++){
        int k0 = kc*64;
        #pragma unroll
        for (int i = 0; i < 4; i++){
            int u = i*256 + tid; int r = u >> 3, seg = u & 7;
            cpa16(asu + (r*HPAD + seg*4)*4, zt + (size_t)r*CM + k0 + seg*8);
            cpa16(bsu + (r*HPAD + seg*4)*4, wb + r*CM + k0 + seg*8);
        }
        CPA_COMMIT();
        CPA_WAIT0();
        __syncthreads();
        mma_f16_128_k64(asu, bsu, wm, wnn, lane, acc);
        __syncthreads();
    }
    #pragma unroll
    for (int mt = 0; mt < 2; mt++){
        int pg0 = p0 + wm*32 + mt*16 + gid;
        #pragma unroll
        for (int nt = 0; nt < 8; nt++){
            int o = o0g + wnn*64 + nt*8 + 2*tig;
            float s0 = sS[o - o0g], s1 = sS[o - o0g + 1];
            float t0 = sT[o - o0g], t1 = sT[o - o0g + 1];
            size_t i00 = ((size_t)b_*C2 + o)*HW + pg0;
            size_t i01 = i00 + HW;
            out[i00]     = x[i00]     + silu_f(acc[mt][nt][0]*s0 + t0);
            out[i01]     = x[i01]     + silu_f(acc[mt][nt][1]*s1 + t1);
            out[i00 + 8] = x[i00 + 8] + silu_f(acc[mt][nt][2]*s0 + t0);
            out[i01 + 8] = x[i01 + 8] + silu_f(acc[mt][nt][3]*s1 + t1);
        }
    }
}

// ---------------- launch ----------------
extern "C" void kernel_launch(void* const* d_in, const int* in_sizes, int n_in,
                              void* d_out, int out_size){
    const float* x     = (const float*)d_in[0];
    const float* cv1_w = (const float*)d_in[1];
    const float* bn1g  = (const float*)d_in[2];
    const float* bn1b  = (const float*)d_in[3];
    const float* bn1m  = (const float*)d_in[4];
    const float* bn1v  = (const float*)d_in[5];
    const float* off_w = (const float*)d_in[6];
    const float* off_b = (const float*)d_in[7];
    const float* dcn_w = (const float*)d_in[8];
    const float* dcn_b = (const float*)d_in[9];
    const float* bn2g  = (const float*)d_in[10];
    const float* bn2b  = (const float*)d_in[11];
    const float* bn2m  = (const float*)d_in[12];
    const float* bn2v  = (const float*)d_in[13];
    const float* cv3_w = (const float*)d_in[14];
    const float* bn3g  = (const float*)d_in[15];
    const float* bn3b  = (const float*)d_in[16];
    const float* bn3m  = (const float*)d_in[17];
    const float* bn3v  = (const float*)d_in[18];
    float* out = (float*)d_out;

    prep_w<<<(N9*CM*CM + 255)/256, 256>>>(cv1_w, off_w, dcn_w, cv3_w);
    k1_mma<<<BSZ*50, 256>>>(x, bn1g, bn1b, bn1m, bn1v);
    k2_mma<<<BSZ*50, 256>>>(off_b);

    int smem_bytes = K3_SMEM_F * 4;  // 111616 B
    cudaFuncSetAttribute(k3_deform_mma, cudaFuncAttributeMaxDynamicSharedMemorySize, smem_bytes);
    k3_deform_mma<<<BSZ*50, 256, smem_bytes>>>(dcn_b, bn2g, bn2b, bn2m, bn2v);

    k4_mma<<<dim3(BSZ*50, 2), 256>>>(x, out, bn3g, bn3b, bn3m, bn3v);
}

// round 14
// speedup vs baseline: 1.0544x; 1.0247x over previous
#include <cuda_runtime.h>
#include <cuda_fp16.h>
#include <math.h>
#include <stdint.h>

#define BSZ   8
#define C1    256
#define C2    256
#define CM    128
#define Hh    80
#define Ww    80
#define HW    6400
#define N9    9
#define KCN   1152      // CM * 9
#define NOFF  27
#define EPSF  1e-5f

// ---------------- scratch (device globals; no runtime alloc) ----------------
__device__ __align__(16) __half g_yh  [BSZ*HW*CM];    // NHWC y (fp16)
__device__ __align__(16) __half g_zh  [BSZ*HW*CM];    // NHWC z (fp16)
__device__ __align__(16) float  g_pred[BSZ*HW*NOFF];  // per-pixel [27] fp32
__device__ __align__(16) __half g_w1h [CM*C1];        // [o][k]
__device__ __align__(16) __half g_w2h [N9*32*CM];     // [n][o pad 32][c]
__device__ __align__(16) __half g_wdh [N9*CM*CM];     // [n][o][c]
__device__ __align__(16) __half g_w3h [C2*CM];        // [o][k]

__device__ __forceinline__ float silu_f(float v){ return v / (1.f + __expf(-v)); }
__device__ __forceinline__ uint32_t s2u(const void* p){
    return (uint32_t)__cvta_generic_to_shared(p);
}
__device__ __forceinline__ void cpa16(uint32_t s, const void* g){
    asm volatile("cp.async.cg.shared.global [%0], [%1], 16;" :: "r"(s), "l"(g));
}
#define CPA_COMMIT() asm volatile("cp.async.commit_group;" ::: "memory")
#define CPA_WAIT0()  asm volatile("cp.async.wait_group 0;" ::: "memory")

// row pitch in u32: 64 halves data (32 u32) + pad 4 -> 144B rows
#define HPAD 36

#define MMA_F16(accq, a0,a1,a2,a3, b0,b1) \
    asm volatile("mma.sync.aligned.m16n8k16.row.col.f32.f16.f16.f32 " \
        "{%0,%1,%2,%3}, {%4,%5,%6,%7}, {%8,%9}, {%0,%1,%2,%3};" \
        : "+f"((accq)[0]), "+f"((accq)[1]), "+f"((accq)[2]), "+f"((accq)[3]) \
        : "r"(a0), "r"(a1), "r"(a2), "r"(a3), "r"(b0), "r"(b1))

__device__ __forceinline__ void ldsm4(uint32_t* r, uint32_t a){
    asm volatile("ldmatrix.sync.aligned.m8n8.x4.shared.b16 {%0,%1,%2,%3}, [%4];"
        : "=r"(r[0]), "=r"(r[1]), "=r"(r[2]), "=r"(r[3]) : "r"(a));
}

// 128x128 warp-tiled fp16 mma, K-chunk = 64, ldmatrix fragment loads.
__device__ __forceinline__ void mma_f16_128_k64(uint32_t asu, uint32_t bsu,
        int wm, int wnn, int lane, float acc[2][8][4]){
    int l7 = lane & 7;
    uint32_t aBase = asu + (uint32_t)((wm*32 + ((lane>>3)&1)*8 + l7)*HPAD)*4 + (lane>>4)*16;
    uint32_t bBase = bsu + (uint32_t)((wnn*64 + ((lane>>4)&1)*8 + l7)*HPAD)*4 + ((lane>>3)&1)*16;
    #pragma unroll
    for (int kk = 0; kk < 4; kk++){
        uint32_t a[2][4];
        #pragma unroll
        for (int mt = 0; mt < 2; mt++)
            ldsm4(a[mt], aBase + (uint32_t)(mt*16*HPAD)*4 + kk*32);
        #pragma unroll
        for (int ntp = 0; ntp < 4; ntp++){
            uint32_t b[4];
            ldsm4(b, bBase + (uint32_t)(ntp*16*HPAD)*4 + kk*32);
            #pragma unroll
            for (int mt = 0; mt < 2; mt++){
                MMA_F16(acc[mt][2*ntp],   a[mt][0],a[mt][1],a[mt][2],a[mt][3], b[0],b[1]);
                MMA_F16(acc[mt][2*ntp+1], a[mt][0],a[mt][1],a[mt][2],a[mt][3], b[2],b[3]);
            }
        }
    }
}

// ---------------- K0: weight conversions/reshapes to fp16 ----------------
__global__ void prep_w(const float* __restrict__ w1, const float* __restrict__ w2,
                       const float* __restrict__ wd, const float* __restrict__ w3){
    int i = blockIdx.x*blockDim.x + threadIdx.x;
    if (i < CM*C1)  g_w1h[i] = __float2half(w1[i]);
    if (i < C2*CM)  g_w3h[i] = __float2half(w3[i]);
    if (i < N9*32*CM){
        int n = i/(32*CM); int o = (i/CM) & 31; int c = i % CM;
        g_w2h[i] = (o < NOFF) ? __float2half(w2[o*KCN + c*9 + n]) : __float2half(0.f);
    }
    if (i < N9*CM*CM){
        int n = i/(CM*CM); int rest = i%(CM*CM); int o = rest/CM, c = rest%CM;
        g_wdh[i] = __float2half(wd[o*KCN + c*9 + n]);
    }
}

// ---------------- K1: conv1x1(256->128) + bn1 + silu -> g_yh (NHWC fp16), direct NCHW A ----------------
__global__ void __launch_bounds__(256, 2) k1_mma(const float* __restrict__ x,
        const float* __restrict__ g1, const float* __restrict__ b1,
        const float* __restrict__ m1, const float* __restrict__ v1){
    __shared__ __align__(16) uint32_t As[128*HPAD];
    __shared__ __align__(16) uint32_t Bs[128*HPAD];
    __shared__ float sS[128], sT[128];
    int blk = blockIdx.x;
    int b_ = blk / 50;
    int p0 = (blk % 50) * 128;
    int tid = threadIdx.x, warp = tid >> 5, lane = tid & 31;
    int wm = warp & 3, wnn = warp >> 2, gid = lane >> 2, tig = lane & 3;
    if (tid < 128){
        float s = g1[tid] * rsqrtf(v1[tid] + EPSF);
        sS[tid] = s;
        sT[tid] = b1[tid] - m1[tid]*s;
    }
    float acc[2][8][4] = {};
    const float* xb = x + (size_t)b_*C1*HW + p0;
    uint32_t asu = s2u(As), bsu = s2u(Bs);
    for (int kc = 0; kc < 4; kc++){
        int k0 = kc*64;
        // B: cp.async from pre-converted fp16 weights
        #pragma unroll
        for (int i = 0; i < 4; i++){
            int u = i*256 + tid; int r = u >> 3, seg = u & 7;
            cpa16(bsu + (r*HPAD + seg*4)*4, g_w1h + r*C1 + k0 + seg*8);
        }
        CPA_COMMIT();
        // A: direct NCHW fp32 load (coalesced over px), pack half2 along k
        #pragma unroll
        for (int i = 0; i < 16; i++){
            int e = i*256 + tid; int j = e >> 7, px = e & 127;
            float f0 = xb[(size_t)(k0 + 2*j)*HW + px];
            float f1 = xb[(size_t)(k0 + 2*j + 1)*HW + px];
            __half2 hh = __float22half2_rn(make_float2(f0, f1));
            As[px*HPAD + j] = *(uint32_t*)&hh;
        }
        CPA_WAIT0();
        __syncthreads();
        mma_f16_128_k64(asu, bsu, wm, wnn, lane, acc);
        __syncthreads();
    }
    #pragma unroll
    for (int mt = 0; mt < 2; mt++){
        int r0 = wm*32 + mt*16 + gid;
        __half2* z0 = (__half2*)(g_yh + (size_t)(b_*HW + p0 + r0)*CM);
        __half2* z1 = (__half2*)(g_yh + (size_t)(b_*HW + p0 + r0 + 8)*CM);
        #pragma unroll
        for (int nt = 0; nt < 8; nt++){
            int cb = wnn*64 + nt*8 + 2*tig;
            float s0 = sS[cb], s1 = sS[cb+1], t0 = sT[cb], t1 = sT[cb+1];
            z0[cb>>1] = __float22half2_rn(make_float2(
                silu_f(acc[mt][nt][0]*s0 + t0), silu_f(acc[mt][nt][1]*s1 + t1)));
            z1[cb>>1] = __float22half2_rn(make_float2(
                silu_f(acc[mt][nt][2]*s0 + t0), silu_f(acc[mt][nt][3]*s1 + t1)));
        }
    }
}

// ---------------- K2: conv3x3(128->27) via fp16 mma (implicit im2col) -> g_pred ----------------
__global__ void __launch_bounds__(256, 4) k2_mma(const float* __restrict__ offb){
    __shared__ __align__(16) uint32_t As[128*HPAD];
    __shared__ __align__(16) uint32_t Bs[32*HPAD];
    __shared__ float sB[32];
    int blk = blockIdx.x;
    int b_ = blk / 50;
    int p0 = (blk % 50) * 128;
    int tid = threadIdx.x, warp = tid >> 5, lane = tid & 31;
    int gid = lane >> 2, tig = lane & 3;
    int sub = lane >> 3, grp = lane & 7;     // 4 px x 8 channel-groups (8ch each)
    int l7 = lane & 7;
    if (tid < 32) sB[tid] = (tid < NOFF) ? offb[tid] : 0.f;
    uint32_t asu = s2u(As), bsu = s2u(Bs);
    uint32_t aBase = asu + (uint32_t)((warp*16 + ((lane>>3)&1)*8 + l7)*HPAD)*4 + (lane>>4)*16;
    uint32_t bBase = bsu + (uint32_t)((((lane>>4)&1)*8 + l7)*HPAD)*4 + ((lane>>3)&1)*16;

    float acc[4][4] = {};
    for (int it = 0; it < 18; it++){
        int n  = it >> 1;
        int c0 = (it & 1) << 6;
        int dy = n/3 - 1, dx = n%3 - 1;
        {
            int o = tid >> 3, seg = tid & 7;
            cpa16(bsu + (o*HPAD + seg*4)*4, g_w2h + (size_t)n*32*CM + o*CM + c0 + seg*8);
        }
        CPA_COMMIT();
        #pragma unroll
        for (int p = 0; p < 4; p++){
            int px = warp*16 + p*4 + sub;
            int pg = p0 + px, h = pg / Ww, w = pg % Ww;
            int sy = h + dy, sx = w + dx;
            bool ok = (sy >= 0) & (sy < Hh) & (sx >= 0) & (sx < Ww);
            uint4 t = make_uint4(0u,0u,0u,0u);
            if (ok)
                t = *(const uint4*)(g_yh + (size_t)(b_*HW + sy*Ww + sx)*CM + c0 + grp*8);
            *(uint4*)(As + px*HPAD + grp*4) = t;
        }
        CPA_WAIT0();
        __syncthreads();
        #pragma unroll
        for (int kk = 0; kk < 4; kk++){
            uint32_t a[4];
            ldsm4(a, aBase + kk*32);
            #pragma unroll
            for (int ntp = 0; ntp < 2; ntp++){
                uint32_t b[4];
                ldsm4(b, bBase + (uint32_t)(ntp*16*HPAD)*4 + kk*32);
                MMA_F16(acc[2*ntp],   a[0],a[1],a[2],a[3], b[0],b[1]);
                MMA_F16(acc[2*ntp+1], a[0],a[1],a[2],a[3], b[2],b[3]);
            }
        }
        __syncthreads();
    }
    #pragma unroll
    for (int half = 0; half < 2; half++){
        int px = warp*16 + gid + half*8;
        float* pp = g_pred + (size_t)(b_*HW + p0 + px)*NOFF;
        #pragma unroll
        for (int nt = 0; nt < 4; nt++){
            int c = nt*8 + 2*tig;
            float v0 = acc[nt][half*2 + 0] + sB[c];
            float v1 = acc[nt][half*2 + 1] + sB[c+1];
            if (c >= 18)   v0 = 1.f/(1.f + __expf(-v0));
            if (c+1 >= 18) v1 = 1.f/(1.f + __expf(-v1));
            if (c < NOFF)   pp[c]   = v0;
            if (c+1 < NOFF) pp[c+1] = v1;
        }
    }
}

// ---------------- K3: deform conv via fp16 mma, K-chunk 64, hfma2 gather ----------------
#define K3_F_AS0  0
#define K3_F_AS1  (128*HPAD)
#define K3_F_BS0  (2*128*HPAD)
#define K3_F_BS1  (3*128*HPAD)
#define K3_F_IDX  (4*128*HPAD)
#define K3_F_WTH  (K3_F_IDX + 4608)          // 1152 uint2 = 2304 floats
#define K3_F_S    (K3_F_WTH + 2304)
#define K3_F_T    (K3_F_S + 128)
#define K3_SMEM_F (K3_F_T + 128)

__global__ void __launch_bounds__(256, 2) k3_deform_mma(const float* __restrict__ dcnb,
        const float* __restrict__ g2, const float* __restrict__ b2,
        const float* __restrict__ m2, const float* __restrict__ v2){
    extern __shared__ float sm[];
    uint32_t* AsB[2] = { (uint32_t*)(sm + K3_F_AS0), (uint32_t*)(sm + K3_F_AS1) };
    int4*  sIdx = (int4*)(sm + K3_F_IDX);
    uint2* sWtH = (uint2*)(sm + K3_F_WTH);
    float* sS = sm + K3_F_S;
    float* sT = sm + K3_F_T;

    int blk = blockIdx.x;
    int b_ = blk / 50;
    int p0 = (blk % 50) * 128;
    int tid = threadIdx.x, warp = tid >> 5, lane = tid & 31;

    // setup: precompute bilinear corner indices + mask/validity-folded weights (fp16 packed)
    for (int pr = tid; pr < 128*9; pr += 256){
        int p = pr / 9, nn = pr % 9;
        int pg = p0 + p, h = pg / Ww, w = pg % Ww;
        size_t pb = (size_t)(b_*HW + pg) * NOFF;
        float py = (float)(h - 1 + nn/3) + g_pred[pb + 2*nn];
        float qx = (float)(w - 1 + nn%3) + g_pred[pb + 2*nn + 1];
        float mk = g_pred[pb + 18 + nn];
        float y0f = floorf(py), x0f = floorf(qx);
        float wy = py - y0f, wx = qx - x0f;
        int iy0 = (int)y0f, ix0 = (int)x0f, iy1 = iy0 + 1, ix1 = ix0 + 1;
        float vy0 = (iy0 >= 0 && iy0 < Hh) ? 1.f : 0.f;
        float vy1 = (iy1 >= 0 && iy1 < Hh) ? 1.f : 0.f;
        float vx0 = (ix0 >= 0 && ix0 < Ww) ? 1.f : 0.f;
        float vx1 = (ix1 >= 0 && ix1 < Ww) ? 1.f : 0.f;
        int cy0 = min(max(iy0,0),Hh-1), cy1 = min(max(iy1,0),Hh-1);
        int cx0 = min(max(ix0,0),Ww-1), cx1 = min(max(ix1,0),Ww-1);
        int base = b_*HW;
        int4 id;
        id.x = (base + cy0*Ww + cx0)*CM;
        id.y = (base + cy0*Ww + cx1)*CM;
        id.z = (base + cy1*Ww + cx0)*CM;
        id.w = (base + cy1*Ww + cx1)*CM;
        float w00 = (1.f-wy)*(1.f-wx)*mk*vy0*vx0;
        float w01 = (1.f-wy)*wx      *mk*vy0*vx1;
        float w10 = wy*(1.f-wx)      *mk*vy1*vx0;
        float w11 = wy*wx            *mk*vy1*vx1;
        __half2 h01 = __float22half2_rn(make_float2(w00, w01));
        __half2 h23 = __float22half2_rn(make_float2(w10, w11));
        uint2 wp;
        wp.x = *(uint32_t*)&h01;
        wp.y = *(uint32_t*)&h23;
        sIdx[pr] = id;
        sWtH[pr] = wp;
    }
    if (tid < 128){
        float s = g2[tid] * rsqrtf(v2[tid] + EPSF);
        sS[tid] = s;
        sT[tid] = dcnb[tid]*s + b2[tid] - m2[tid]*s;
    }
    __syncthreads();

    int wm = warp & 3, wnn = warp >> 2, gid = lane >> 2, tig = lane & 3;
    int sub = lane >> 3, grp = lane & 7;   // 4 px x 8 channel-groups (8ch each)
    float acc[2][8][4] = {};
    uint32_t asuB[2] = { s2u(AsB[0]), s2u(AsB[1]) };
    uint32_t bsuB[2] = { s2u((uint32_t*)(sm + K3_F_BS0)), s2u((uint32_t*)(sm + K3_F_BS1)) };

    auto fillB = [&](int it, int buf){
        int n = it >> 1, c0 = (it & 1) << 6;
        const __half* wn = g_wdh + (size_t)n*(CM*CM) + c0;
        uint32_t bu = bsuB[buf];
        #pragma unroll
        for (int i = 0; i < 4; i++){
            int u = i*256 + tid; int o = u >> 3, seg = u & 7;
            cpa16(bu + (o*HPAD + seg*4)*4, wn + o*CM + seg*8);
        }
    };
    // gather: 16B corner loads, bilinear blend fully in hfma2
    auto fillA = [&](int it, int buf){
        int n = it >> 1, c0 = (it & 1) << 6;
        const __half* yb = g_yh + c0 + grp*8;
        uint32_t* Ad = AsB[buf];
        #pragma unroll
        for (int p = 0; p < 4; p++){
            int px = warp*16 + p*4 + sub;
            int pr = px*9 + n;
            int4  id = sIdx[pr];
            uint2 wp = sWtH[pr];
            __half2 wpx = *(__half2*)&wp.x;     // (w00, w01)
            __half2 wpy = *(__half2*)&wp.y;     // (w10, w11)
            __half2 w00 = __half2half2(__low2half(wpx));
            __half2 w01 = __half2half2(__high2half(wpx));
            __half2 w10 = __half2half2(__low2half(wpy));
            __half2 w11 = __half2half2(__high2half(wpy));
            uint4 c00 = *(const uint4*)(yb + id.x);
            uint4 c01 = *(const uint4*)(yb + id.y);
            uint4 c10 = *(const uint4*)(yb + id.z);
            uint4 c11 = *(const uint4*)(yb + id.w);
            uint4 t;
            #pragma unroll
            for (int q = 0; q < 4; q++){
                __half2 v = __hmul2(((__half2*)&c00)[q], w00);
                v = __hfma2(((__half2*)&c01)[q], w01, v);
                v = __hfma2(((__half2*)&c10)[q], w10, v);
                v = __hfma2(((__half2*)&c11)[q], w11, v);
                ((__half2*)&t)[q] = v;
            }
            *(uint4*)(Ad + px*HPAD + grp*4) = t;
        }
    };

    // prologue
    fillB(0, 0); CPA_COMMIT();
    fillA(0, 0);
    CPA_WAIT0();
    __syncthreads();

    int cur = 0;
    for (int it = 0; it < 18; it++){
        int nb = cur ^ 1;
        if (it < 17){ fillB(it+1, nb); CPA_COMMIT(); }
        mma_f16_128_k64(asuB[cur], bsuB[cur], wm, wnn, lane, acc);
        if (it < 17) fillA(it+1, nb);
        CPA_WAIT0();
        __syncthreads();
        cur = nb;
    }

    // epilogue: bn2 + silu -> g_zh (fp16 NHWC)
    #pragma unroll
    for (int mt = 0; mt < 2; mt++){
        int r0 = wm*32 + mt*16 + gid;
        __half2* z0 = (__half2*)(g_zh + (size_t)(b_*HW + p0 + r0)*CM);
        __half2* z1 = (__half2*)(g_zh + (size_t)(b_*HW + p0 + r0 + 8)*CM);
        #pragma unroll
        for (int nt = 0; nt < 8; nt++){
            int cb = wnn*64 + nt*8 + 2*tig;
            float s0 = sS[cb], s1 = sS[cb+1], t0 = sT[cb], t1 = sT[cb+1];
            z0[cb>>1] = __float22half2_rn(make_float2(
                silu_f(acc[mt][nt][0]*s0 + t0), silu_f(acc[mt][nt][1]*s1 + t1)));
            z1[cb>>1] = __float22half2_rn(make_float2(
                silu_f(acc[mt][nt][2]*s0 + t0), silu_f(acc[mt][nt][3]*s1 + t1)));
        }
    }
}

// ---------------- K4: conv1x1(128->256) + bn3 + silu + residual -> out (NCHW) ----------------
__global__ void __launch_bounds__(256, 2) k4_mma(const float* __restrict__ x, float* __restrict__ out,
        const float* __restrict__ g3, const float* __restrict__ b3,
        const float* __restrict__ m3, const float* __restrict__ v3){
    __shared__ __align__(16) uint32_t As[128*HPAD];
    __shared__ __align__(16) uint32_t Bs[128*HPAD];
    __shared__ float sS[128], sT[128];
    int blk = blockIdx.x;
    int b_ = blk / 50;
    int p0 = (blk % 50) * 128;
    int o0g = blockIdx.y * 128;
    int tid = threadIdx.x, warp = tid >> 5, lane = tid & 31;
    int wm = warp & 3, wnn = warp >> 2, gid = lane >> 2, tig = lane & 3;
    if (tid < 128){
        int o = o0g + tid;
        float s = g3[o] * rsqrtf(v3[o] + EPSF);
        sS[tid] = s;
        sT[tid] = b3[o] - m3[o]*s;
    }
    float acc[2][8][4] = {};
    const __half* zt = g_zh + (size_t)(b_*HW + p0)*CM;
    const __half* wb = g_w3h + (size_t)o0g*CM;
    uint32_t asu = s2u(As), bsu = s2u(Bs);
    for (int kc = 0; kc < 2; kc++){
        int k0 = kc*64;
        #pragma unroll
        for (int i = 0; i < 4; i++){
            int u = i*256 + tid; int r = u >> 3, seg = u & 7;
            cpa16(asu + (r*HPAD + seg*4)*4, zt + (size_t)r*CM + k0 + seg*8);
            cpa16(bsu + (r*HPAD + seg*4)*4, wb + r*CM + k0 + seg*8);
        }
        CPA_COMMIT();
        CPA_WAIT0();
        __syncthreads();
        mma_f16_128_k64(asu, bsu, wm, wnn, lane, acc);
        __syncthreads();
    }
    #pragma unroll
    for (int mt = 0; mt < 2; mt++){
        int pg0 = p0 + wm*32 + mt*16 + gid;
        #pragma unroll
        for (int nt = 0; nt < 8; nt++){
            int o = o0g + wnn*64 + nt*8 + 2*tig;
            float s0 = sS[o - o0g], s1 = sS[o - o0g + 1];
            float t0 = sT[o - o0g], t1 = sT[o - o0g + 1];
            size_t i00 = ((size_t)b_*C2 + o)*HW + pg0;
            size_t i01 = i00 + HW;
            out[i00]     = x[i00]     + silu_f(acc[mt][nt][0]*s0 + t0);
            out[i01]     = x[i01]     + silu_f(acc[mt][nt][1]*s1 + t1);
            out[i00 + 8] = x[i00 + 8] + silu_f(acc[mt][nt][2]*s0 + t0);
            out[i01 + 8] = x[i01 + 8] + silu_f(acc[mt][nt][3]*s1 + t1);
        }
    }
}

// ---------------- launch ----------------
extern "C" void kernel_launch(void* const* d_in, const int* in_sizes, int n_in,
                              void* d_out, int out_size){
    const float* x     = (const float*)d_in[0];
    const float* cv1_w = (const float*)d_in[1];
    const float* bn1g  = (const float*)d_in[2];
    const float* bn1b  = (const float*)d_in[3];
    const float* bn1m  = (const float*)d_in[4];
    const float* bn1v  = (const float*)d_in[5];
    const float* off_w = (const float*)d_in[6];
    const float* off_b = (const float*)d_in[7];
    const float* dcn_w = (const float*)d_in[8];
    const float* dcn_b = (const float*)d_in[9];
    const float* bn2g  = (const float*)d_in[10];
    const float* bn2b  = (const float*)d_in[11];
    const float* bn2m  = (const float*)d_in[12];
    const float* bn2v  = (const float*)d_in[13];
    const float* cv3_w = (const float*)d_in[14];
    const float* bn3g  = (const float*)d_in[15];
    const float* bn3b  = (const float*)d_in[16];
    const float* bn3m  = (const float*)d_in[17];
    const float* bn3v  = (const float*)d_in[18];
    float* out = (float*)d_out;

    prep_w<<<(N9*CM*CM + 255)/256, 256>>>(cv1_w, off_w, dcn_w, cv3_w);
    k1_mma<<<BSZ*50, 256>>>(x, bn1g, bn1b, bn1m, bn1v);
    k2_mma<<<BSZ*50, 256>>>(off_b);

    int smem_bytes = K3_SMEM_F * 4;  // 102400 B
    cudaFuncSetAttribute(k3_deform_mma, cudaFuncAttributeMaxDynamicSharedMemorySize, smem_bytes);
    k3_deform_mma<<<BSZ*50, 256, smem_bytes>>>(dcn_b, bn2g, bn2b, bn2m, bn2v);

    k4_mma<<<dim3(BSZ*50, 2), 256>>>(x, out, bn3g, bn3b, bn3m, bn3v);
}

// round 15
// speedup vs baseline: 1.2208x; 1.1578x over previous
#include <cuda_runtime.h>
#include <cuda_fp16.h>
#include <math.h>
#include <stdint.h>

#define BSZ   8
#define C1    256
#define C2    256
#define CM    128
#define Hh    80
#define Ww    80
#define HW    6400
#define N9    9
#define KCN   1152      // CM * 9
#define NOFF  27
#define EPSF  1e-5f

// ---------------- scratch (device globals; no runtime alloc) ----------------
__device__ __align__(16) __half g_yh  [BSZ*HW*CM];    // NHWC y (fp16)
__device__ __align__(16) __half g_zh  [BSZ*HW*CM];    // NHWC z (fp16)
__device__ __align__(16) float  g_pred[BSZ*HW*NOFF];  // per-pixel [27] fp32
__device__ __align__(16) __half g_w1h [CM*C1];        // [o][k]
__device__ __align__(16) __half g_w2h [N9*32*CM];     // [n][o pad 32][c]
__device__ __align__(16) __half g_wdh [N9*CM*CM];     // [n][o][c]
__device__ __align__(16) __half g_w3h [C2*CM];        // [o][k]

__device__ __forceinline__ float silu_f(float v){ return v / (1.f + __expf(-v)); }
__device__ __forceinline__ uint32_t s2u(const void* p){
    return (uint32_t)__cvta_generic_to_shared(p);
}
__device__ __forceinline__ void cpa16(uint32_t s, const void* g){
    asm volatile("cp.async.cg.shared.global [%0], [%1], 16;" :: "r"(s), "l"(g));
}
#define CPA_COMMIT() asm volatile("cp.async.commit_group;" ::: "memory")
#define CPA_WAIT0()  asm volatile("cp.async.wait_group 0;" ::: "memory")

// row pitch in u32: 64 halves data (32 u32) + pad 4 -> 144B rows
#define HPAD 36

#define MMA_F16(accq, a0,a1,a2,a3, b0,b1) \
    asm volatile("mma.sync.aligned.m16n8k16.row.col.f32.f16.f16.f32 " \
        "{%0,%1,%2,%3}, {%4,%5,%6,%7}, {%8,%9}, {%0,%1,%2,%3};" \
        : "+f"((accq)[0]), "+f"((accq)[1]), "+f"((accq)[2]), "+f"((accq)[3]) \
        : "r"(a0), "r"(a1), "r"(a2), "r"(a3), "r"(b0), "r"(b1))

__device__ __forceinline__ void ldsm4(uint32_t* r, uint32_t a){
    asm volatile("ldmatrix.sync.aligned.m8n8.x4.shared.b16 {%0,%1,%2,%3}, [%4];"
        : "=r"(r[0]), "=r"(r[1]), "=r"(r[2]), "=r"(r[3]) : "r"(a));
}

// 128x128 warp-tiled fp16 mma, K-chunk = 64 (k2/k4)
__device__ __forceinline__ void mma_f16_128_k64(uint32_t asu, uint32_t bsu,
        int wm, int wnn, int lane, float acc[2][8][4]){
    int l7 = lane & 7;
    uint32_t aBase = asu + (uint32_t)((wm*32 + ((lane>>3)&1)*8 + l7)*HPAD)*4 + (lane>>4)*16;
    uint32_t bBase = bsu + (uint32_t)((wnn*64 + ((lane>>4)&1)*8 + l7)*HPAD)*4 + ((lane>>3)&1)*16;
    #pragma unroll
    for (int kk = 0; kk < 4; kk++){
        uint32_t a[2][4];
        #pragma unroll
        for (int mt = 0; mt < 2; mt++)
            ldsm4(a[mt], aBase + (uint32_t)(mt*16*HPAD)*4 + kk*32);
        #pragma unroll
        for (int ntp = 0; ntp < 4; ntp++){
            uint32_t b[4];
            ldsm4(b, bBase + (uint32_t)(ntp*16*HPAD)*4 + kk*32);
            #pragma unroll
            for (int mt = 0; mt < 2; mt++){
                MMA_F16(acc[mt][2*ntp],   a[mt][0],a[mt][1],a[mt][2],a[mt][3], b[0],b[1]);
                MMA_F16(acc[mt][2*ntp+1], a[mt][0],a[mt][1],a[mt][2],a[mt][3], b[2],b[3]);
            }
        }
    }
}

// 64x128 warp-tiled fp16 mma, K-chunk = 64 (k1/k3): warp grid 2m x 4n, acc[2][4][4]
__device__ __forceinline__ void mma_f16_64_k64(uint32_t asu, uint32_t bsu,
        int wm, int wn, int lane, float acc[2][4][4]){
    int l7 = lane & 7;
    uint32_t aBase = asu + (uint32_t)((wm*32 + ((lane>>3)&1)*8 + l7)*HPAD)*4 + (lane>>4)*16;
    uint32_t bBase = bsu + (uint32_t)((wn*32 + ((lane>>4)&1)*8 + l7)*HPAD)*4 + ((lane>>3)&1)*16;
    #pragma unroll
    for (int kk = 0; kk < 4; kk++){
        uint32_t a[2][4];
        #pragma unroll
        for (int mt = 0; mt < 2; mt++)
            ldsm4(a[mt], aBase + (uint32_t)(mt*16*HPAD)*4 + kk*32);
        #pragma unroll
        for (int ntp = 0; ntp < 2; ntp++){
            uint32_t b[4];
            ldsm4(b, bBase + (uint32_t)(ntp*16*HPAD)*4 + kk*32);
            #pragma unroll
            for (int mt = 0; mt < 2; mt++){
                MMA_F16(acc[mt][2*ntp],   a[mt][0],a[mt][1],a[mt][2],a[mt][3], b[0],b[1]);
                MMA_F16(acc[mt][2*ntp+1], a[mt][0],a[mt][1],a[mt][2],a[mt][3], b[2],b[3]);
            }
        }
    }
}

// ---------------- K0: weight conversions/reshapes to fp16 ----------------
__global__ void prep_w(const float* __restrict__ w1, const float* __restrict__ w2,
                       const float* __restrict__ wd, const float* __restrict__ w3){
    int i = blockIdx.x*blockDim.x + threadIdx.x;
    if (i < CM*C1)  g_w1h[i] = __float2half(w1[i]);
    if (i < C2*CM)  g_w3h[i] = __float2half(w3[i]);
    if (i < N9*32*CM){
        int n = i/(32*CM); int o = (i/CM) & 31; int c = i % CM;
        g_w2h[i] = (o < NOFF) ? __float2half(w2[o*KCN + c*9 + n]) : __float2half(0.f);
    }
    if (i < N9*CM*CM){
        int n = i/(CM*CM); int rest = i%(CM*CM); int o = rest/CM, c = rest%CM;
        g_wdh[i] = __float2half(wd[o*KCN + c*9 + n]);
    }
}

// ---------------- K1: conv1x1(256->128) + bn1 + silu -> g_yh, 64px tiles, occ 3 ----------------
__global__ void __launch_bounds__(256, 3) k1_mma(const float* __restrict__ x,
        const float* __restrict__ g1, const float* __restrict__ b1,
        const float* __restrict__ m1, const float* __restrict__ v1){
    __shared__ __align__(16) uint32_t As[64*HPAD];
    __shared__ __align__(16) uint32_t Bs[128*HPAD];
    __shared__ float sS[128], sT[128];
    int blk = blockIdx.x;
    int b_ = blk / 100;
    int p0 = (blk % 100) * 64;
    int tid = threadIdx.x, warp = tid >> 5, lane = tid & 31;
    int wm = warp & 1, wn = warp >> 1, gid = lane >> 2, tig = lane & 3;
    if (tid < 128){
        float s = g1[tid] * rsqrtf(v1[tid] + EPSF);
        sS[tid] = s;
        sT[tid] = b1[tid] - m1[tid]*s;
    }
    float acc[2][4][4] = {};
    const float* xb = x + (size_t)b_*C1*HW + p0;
    uint32_t asu = s2u(As), bsu = s2u(Bs);
    for (int kc = 0; kc < 4; kc++){
        int k0 = kc*64;
        #pragma unroll
        for (int i = 0; i < 4; i++){
            int u = i*256 + tid; int r = u >> 3, seg = u & 7;
            cpa16(bsu + (r*HPAD + seg*4)*4, g_w1h + r*C1 + k0 + seg*8);
        }
        CPA_COMMIT();
        // A: direct NCHW fp32 load (coalesced over px), pack half2 along k
        #pragma unroll
        for (int i = 0; i < 8; i++){
            int e = i*256 + tid; int j = e >> 6, px = e & 63;
            float f0 = xb[(size_t)(k0 + 2*j)*HW + px];
            float f1 = xb[(size_t)(k0 + 2*j + 1)*HW + px];
            __half2 hh = __float22half2_rn(make_float2(f0, f1));
            As[px*HPAD + j] = *(uint32_t*)&hh;
        }
        CPA_WAIT0();
        __syncthreads();
        mma_f16_64_k64(asu, bsu, wm, wn, lane, acc);
        __syncthreads();
    }
    #pragma unroll
    for (int mt = 0; mt < 2; mt++){
        int r0 = wm*32 + mt*16 + gid;
        __half2* z0 = (__half2*)(g_yh + (size_t)(b_*HW + p0 + r0)*CM);
        __half2* z1 = (__half2*)(g_yh + (size_t)(b_*HW + p0 + r0 + 8)*CM);
        #pragma unroll
        for (int nt = 0; nt < 4; nt++){
            int cb = wn*32 + nt*8 + 2*tig;
            float s0 = sS[cb], s1 = sS[cb+1], t0 = sT[cb], t1 = sT[cb+1];
            z0[cb>>1] = __float22half2_rn(make_float2(
                silu_f(acc[mt][nt][0]*s0 + t0), silu_f(acc[mt][nt][1]*s1 + t1)));
            z1[cb>>1] = __float22half2_rn(make_float2(
                silu_f(acc[mt][nt][2]*s0 + t0), silu_f(acc[mt][nt][3]*s1 + t1)));
        }
    }
}

// ---------------- K2: conv3x3(128->27) via fp16 mma (implicit im2col) -> g_pred ----------------
__global__ void __launch_bounds__(256, 4) k2_mma(const float* __restrict__ offb){
    __shared__ __align__(16) uint32_t As[128*HPAD];
    __shared__ __align__(16) uint32_t Bs[32*HPAD];
    __shared__ float sB[32];
    int blk = blockIdx.x;
    int b_ = blk / 50;
    int p0 = (blk % 50) * 128;
    int tid = threadIdx.x, warp = tid >> 5, lane = tid & 31;
    int gid = lane >> 2, tig = lane & 3;
    int sub = lane >> 3, grp = lane & 7;
    int l7 = lane & 7;
    if (tid < 32) sB[tid] = (tid < NOFF) ? offb[tid] : 0.f;
    uint32_t asu = s2u(As), bsu = s2u(Bs);
    uint32_t aBase = asu + (uint32_t)((warp*16 + ((lane>>3)&1)*8 + l7)*HPAD)*4 + (lane>>4)*16;
    uint32_t bBase = bsu + (uint32_t)((((lane>>4)&1)*8 + l7)*HPAD)*4 + ((lane>>3)&1)*16;

    float acc[4][4] = {};
    for (int it = 0; it < 18; it++){
        int n  = it >> 1;
        int c0 = (it & 1) << 6;
        int dy = n/3 - 1, dx = n%3 - 1;
        {
            int o = tid >> 3, seg = tid & 7;
            cpa16(bsu + (o*HPAD + seg*4)*4, g_w2h + (size_t)n*32*CM + o*CM + c0 + seg*8);
        }
        CPA_COMMIT();
        #pragma unroll
        for (int p = 0; p < 4; p++){
            int px = warp*16 + p*4 + sub;
            int pg = p0 + px, h = pg / Ww, w = pg % Ww;
            int sy = h + dy, sx = w + dx;
            bool ok = (sy >= 0) & (sy < Hh) & (sx >= 0) & (sx < Ww);
            uint4 t = make_uint4(0u,0u,0u,0u);
            if (ok)
                t = *(const uint4*)(g_yh + (size_t)(b_*HW + sy*Ww + sx)*CM + c0 + grp*8);
            *(uint4*)(As + px*HPAD + grp*4) = t;
        }
        CPA_WAIT0();
        __syncthreads();
        #pragma unroll
        for (int kk = 0; kk < 4; kk++){
            uint32_t a[4];
            ldsm4(a, aBase + kk*32);
            #pragma unroll
            for (int ntp = 0; ntp < 2; ntp++){
                uint32_t b[4];
                ldsm4(b, bBase + (uint32_t)(ntp*16*HPAD)*4 + kk*32);
                MMA_F16(acc[2*ntp],   a[0],a[1],a[2],a[3], b[0],b[1]);
                MMA_F16(acc[2*ntp+1], a[0],a[1],a[2],a[3], b[2],b[3]);
            }
        }
        __syncthreads();
    }
    #pragma unroll
    for (int half = 0; half < 2; half++){
        int px = warp*16 + gid + half*8;
        float* pp = g_pred + (size_t)(b_*HW + p0 + px)*NOFF;
        #pragma unroll
        for (int nt = 0; nt < 4; nt++){
            int c = nt*8 + 2*tig;
            float v0 = acc[nt][half*2 + 0] + sB[c];
            float v1 = acc[nt][half*2 + 1] + sB[c+1];
            if (c >= 18)   v0 = 1.f/(1.f + __expf(-v0));
            if (c+1 >= 18) v1 = 1.f/(1.f + __expf(-v1));
            if (c < NOFF)   pp[c]   = v0;
            if (c+1 < NOFF) pp[c+1] = v1;
        }
    }
}

// ---------------- K3: deform conv, 64px tiles, occ 3, hfma2 gather ----------------
// floats: As0 64*36, As1 64*36, Bs0 128*36, Bs1 128*36, idxP 576, wtH 1152, S 128, T 128
#define K3_F_AS0  0
#define K3_F_AS1  (64*HPAD)
#define K3_F_BS0  (2*64*HPAD)
#define K3_F_BS1  (2*64*HPAD + 128*HPAD)
#define K3_F_IDX  (2*64*HPAD + 2*128*HPAD)
#define K3_F_WTH  (K3_F_IDX + 576)
#define K3_F_S    (K3_F_WTH + 1152)
#define K3_F_T    (K3_F_S + 128)
#define K3_SMEM_F (K3_F_T + 128)

__global__ void __launch_bounds__(256, 3) k3_deform_mma(const float* __restrict__ dcnb,
        const float* __restrict__ g2, const float* __restrict__ b2,
        const float* __restrict__ m2, const float* __restrict__ v2){
    extern __shared__ float sm[];
    uint32_t* AsB[2] = { (uint32_t*)(sm + K3_F_AS0), (uint32_t*)(sm + K3_F_AS1) };
    uint32_t* sIdxP = (uint32_t*)(sm + K3_F_IDX);
    uint2*    sWtH  = (uint2*)(sm + K3_F_WTH);
    float* sS = sm + K3_F_S;
    float* sT = sm + K3_F_T;

    int blk = blockIdx.x;
    int b_ = blk / 100;
    int p0 = (blk % 100) * 64;
    int tid = threadIdx.x, warp = tid >> 5, lane = tid & 31;

    // setup: bilinear corner base index (packed with dy/dx bits) + fp16 weights
    for (int pr = tid; pr < 64*9; pr += 256){
        int p = pr / 9, nn = pr % 9;
        int pg = p0 + p, h = pg / Ww, w = pg % Ww;
        size_t pb = (size_t)(b_*HW + pg) * NOFF;
        float py = (float)(h - 1 + nn/3) + g_pred[pb + 2*nn];
        float qx = (float)(w - 1 + nn%3) + g_pred[pb + 2*nn + 1];
        float mk = g_pred[pb + 18 + nn];
        float y0f = floorf(py), x0f = floorf(qx);
        float wy = py - y0f, wx = qx - x0f;
        int iy0 = (int)y0f, ix0 = (int)x0f, iy1 = iy0 + 1, ix1 = ix0 + 1;
        float vy0 = (iy0 >= 0 && iy0 < Hh) ? 1.f : 0.f;
        float vy1 = (iy1 >= 0 && iy1 < Hh) ? 1.f : 0.f;
        float vx0 = (ix0 >= 0 && ix0 < Ww) ? 1.f : 0.f;
        float vx1 = (ix1 >= 0 && ix1 < Ww) ? 1.f : 0.f;
        int cy0 = min(max(iy0,0),Hh-1), cy1 = min(max(iy1,0),Hh-1);
        int cx0 = min(max(ix0,0),Ww-1), cx1 = min(max(ix1,0),Ww-1);
        uint32_t base = (uint32_t)((b_*HW + cy0*Ww + cx0)*CM);
        uint32_t dxb = (uint32_t)(cx1 - cx0);   // 0 or 1
        uint32_t dyb = (uint32_t)(cy1 - cy0);   // 0 or 1
        float w00 = (1.f-wy)*(1.f-wx)*mk*vy0*vx0;
        float w01 = (1.f-wy)*wx      *mk*vy0*vx1;
        float w10 = wy*(1.f-wx)      *mk*vy1*vx0;
        float w11 = wy*wx            *mk*vy1*vx1;
        __half2 h01 = __float22half2_rn(make_float2(w00, w01));
        __half2 h23 = __float22half2_rn(make_float2(w10, w11));
        uint2 wp;
        wp.x = *(uint32_t*)&h01;
        wp.y = *(uint32_t*)&h23;
        sIdxP[pr] = (base << 2) | (dyb << 1) | dxb;
        sWtH[pr]  = wp;
    }
    if (tid < 128){
        float s = g2[tid] * rsqrtf(v2[tid] + EPSF);
        sS[tid] = s;
        sT[tid] = dcnb[tid]*s + b2[tid] - m2[tid]*s;
    }
    __syncthreads();

    int wm = warp & 1, wn = warp >> 1, gid = lane >> 2, tig = lane & 3;
    int sub = lane >> 3, grp = lane & 7;
    float acc[2][4][4] = {};
    uint32_t asuB[2] = { s2u(AsB[0]), s2u(AsB[1]) };
    uint32_t bsuB[2] = { s2u((uint32_t*)(sm + K3_F_BS0)), s2u((uint32_t*)(sm + K3_F_BS1)) };

    auto fillB = [&](int it, int buf){
        int n = it >> 1, c0 = (it & 1) << 6;
        const __half* wn_ = g_wdh + (size_t)n*(CM*CM) + c0;
        uint32_t bu = bsuB[buf];
        #pragma unroll
        for (int i = 0; i < 4; i++){
            int u = i*256 + tid; int o = u >> 3, seg = u & 7;
            cpa16(bu + (o*HPAD + seg*4)*4, wn_ + o*CM + seg*8);
        }
    };
    // gather: 2 passes of (4 px x 8 groups), hfma2 blend
    auto fillA = [&](int it, int buf){
        int n = it >> 1, c0 = (it & 1) << 6;
        const __half* yb = g_yh + c0 + grp*8;
        uint32_t* Ad = AsB[buf];
        #pragma unroll
        for (int p = 0; p < 2; p++){
            int px = warp*8 + p*4 + sub;
            int pr = px*9 + n;
            uint32_t v = sIdxP[pr];
            uint2 wp = sWtH[pr];
            int i00 = (int)(v >> 2);
            int ddx = (int)(v & 1u) * CM;
            int ddy = (int)(v & 2u) * (Ww*CM/2);
            int i01 = i00 + ddx;
            int i10 = i00 + ddy;
            int i11 = i01 + ddy;
            __half2 wpx = *(__half2*)&wp.x;
            __half2 wpy = *(__half2*)&wp.y;
            __half2 w00 = __half2half2(__low2half(wpx));
            __half2 w01 = __half2half2(__high2half(wpx));
            __half2 w10 = __half2half2(__low2half(wpy));
            __half2 w11 = __half2half2(__high2half(wpy));
            uint4 c00 = *(const uint4*)(yb + i00);
            uint4 c01 = *(const uint4*)(yb + i01);
            uint4 c10 = *(const uint4*)(yb + i10);
            uint4 c11 = *(const uint4*)(yb + i11);
            uint4 t;
            #pragma unroll
            for (int q = 0; q < 4; q++){
                __half2 vv = __hmul2(((__half2*)&c00)[q], w00);
                vv = __hfma2(((__half2*)&c01)[q], w01, vv);
                vv = __hfma2(((__half2*)&c10)[q], w10, vv);
                vv = __hfma2(((__half2*)&c11)[q], w11, vv);
                ((__half2*)&t)[q] = vv;
            }
            *(uint4*)(Ad + px*HPAD + grp*4) = t;
        }
    };

    // prologue
    fillB(0, 0); CPA_COMMIT();
    fillA(0, 0);
    CPA_WAIT0();
    __syncthreads();

    int cur = 0;
    for (int it = 0; it < 18; it++){
        int nb = cur ^ 1;
        if (it < 17){ fillB(it+1, nb); CPA_COMMIT(); }
        mma_f16_64_k64(asuB[cur], bsuB[cur], wm, wn, lane, acc);
        if (it < 17) fillA(it+1, nb);
        CPA_WAIT0();
        __syncthreads();
        cur = nb;
    }

    // epilogue: bn2 + silu -> g_zh (fp16 NHWC)
    #pragma unroll
    for (int mt = 0; mt < 2; mt++){
        int r0 = wm*32 + mt*16 + gid;
        __half2* z0 = (__half2*)(g_zh + (size_t)(b_*HW + p0 + r0)*CM);
        __half2* z1 = (__half2*)(g_zh + (size_t)(b_*HW + p0 + r0 + 8)*CM);
        #pragma unroll
        for (int nt = 0; nt < 4; nt++){
            int cb = wn*32 + nt*8 + 2*tig;
            float s0 = sS[cb], s1 = sS[cb+1], t0 = sT[cb], t1 = sT[cb+1];
            z0[cb>>1] = __float22half2_rn(make_float2(
                silu_f(acc[mt][nt][0]*s0 + t0), silu_f(acc[mt][nt][1]*s1 + t1)));
            z1[cb>>1] = __float22half2_rn(make_float2(
                silu_f(acc[mt][nt][2]*s0 + t0), silu_f(acc[mt][nt][3]*s1 + t1)));
        }
    }
}

// ---------------- K4: conv1x1(128->256) + bn3 + silu + residual -> out (NCHW) ----------------
__global__ void __launch_bounds__(256, 2) k4_mma(const float* __restrict__ x, float* __restrict__ out,
        const float* __restrict__ g3, const float* __restrict__ b3,
        const float* __restrict__ m3, const float* __restrict__ v3){
    __shared__ __align__(16) uint32_t As[128*HPAD];
    __shared__ __align__(16) uint32_t Bs[128*HPAD];
    __shared__ float sS[128], sT[128];
    int blk = blockIdx.x;
    int b_ = blk / 50;
    int p0 = (blk % 50) * 128;
    int o0g = blockIdx.y * 128;
    int tid = threadIdx.x, warp = tid >> 5, lane = tid & 31;
    int wm = warp & 3, wnn = warp >> 2, gid = lane >> 2, tig = lane & 3;
    if (tid < 128){
        int o = o0g + tid;
        float s = g3[o] * rsqrtf(v3[o] + EPSF);
        sS[tid] = s;
        sT[tid] = b3[o] - m3[o]*s;
    }
    float acc[2][8][4] = {};
    const __half* zt = g_zh + (size_t)(b_*HW + p0)*CM;
    const __half* wb = g_w3h + (size_t)o0g*CM;
    uint32_t asu = s2u(As), bsu = s2u(Bs);
    for (int kc = 0; kc < 2; kc++){
        int k0 = kc*64;
        #pragma unroll
        for (int i = 0; i < 4; i++){
            int u = i*256 + tid; int r = u >> 3, seg = u & 7;
            cpa16(asu + (r*HPAD + seg*4)*4, zt + (size_t)r*CM + k0 + seg*8);
            cpa16(bsu + (r*HPAD + seg*4)*4, wb + r*CM + k0 + seg*8);
        }
        CPA_COMMIT();
        CPA_WAIT0();
        __syncthreads();
        mma_f16_128_k64(asu, bsu, wm, wnn, lane, acc);
        __syncthreads();
    }
    #pragma unroll
    for (int mt = 0; mt < 2; mt++){
        int pg0 = p0 + wm*32 + mt*16 + gid;
        #pragma unroll
        for (int nt = 0; nt < 8; nt++){
            int o = o0g + wnn*64 + nt*8 + 2*tig;
            float s0 = sS[o - o0g], s1 = sS[o - o0g + 1];
            float t0 = sT[o - o0g], t1 = sT[o - o0g + 1];
            size_t i00 = ((size_t)b_*C2 + o)*HW + pg0;
            size_t i01 = i00 + HW;
            out[i00]     = x[i00]     + silu_f(acc[mt][nt][0]*s0 + t0);
            out[i01]     = x[i01]     + silu_f(acc[mt][nt][1]*s1 + t1);
            out[i00 + 8] = x[i00 + 8] + silu_f(acc[mt][nt][2]*s0 + t0);
            out[i01 + 8] = x[i01 + 8] + silu_f(acc[mt][nt][3]*s1 + t1);
        }
    }
}

// ---------------- launch ----------------
extern "C" void kernel_launch(void* const* d_in, const int* in_sizes, int n_in,
                              void* d_out, int out_size){
    const float* x     = (const float*)d_in[0];
    const float* cv1_w = (const float*)d_in[1];
    const float* bn1g  = (const float*)d_in[2];
    const float* bn1b  = (const float*)d_in[3];
    const float* bn1m  = (const float*)d_in[4];
    const float* bn1v  = (const float*)d_in[5];
    const float* off_w = (const float*)d_in[6];
    const float* off_b = (const float*)d_in[7];
    const float* dcn_w = (const float*)d_in[8];
    const float* dcn_b = (const float*)d_in[9];
    const float* bn2g  = (const float*)d_in[10];
    const float* bn2b  = (const float*)d_in[11];
    const float* bn2m  = (const float*)d_in[12];
    const float* bn2v  = (const float*)d_in[13];
    const float* cv3_w = (const float*)d_in[14];
    const float* bn3g  = (const float*)d_in[15];
    const float* bn3b  = (const float*)d_in[16];
    const float* bn3m  = (const float*)d_in[17];
    const float* bn3v  = (const float*)d_in[18];
    float* out = (float*)d_out;

    prep_w<<<(N9*CM*CM + 255)/256, 256>>>(cv1_w, off_w, dcn_w, cv3_w);
    k1_mma<<<BSZ*100, 256>>>(x, bn1g, bn1b, bn1m, bn1v);
    k2_mma<<<BSZ*50, 256>>>(off_b);

    int smem_bytes = K3_SMEM_F * 4;  // 63232 B
    cudaFuncSetAttribute(k3_deform_mma, cudaFuncAttributeMaxDynamicSharedMemorySize, smem_bytes);
    k3_deform_mma<<<BSZ*100, 256, smem_bytes>>>(dcn_b, bn2g, bn2b, bn2m, bn2v);

    k4_mma<<<dim3(BSZ*50, 2), 256>>>(x, out, bn3g, bn3b, bn3m, bn3v);
}

// round 17
// speedup vs baseline: 1.2344x; 1.0111x over previous
#include <cuda_runtime.h>
#include <cuda_fp16.h>
#include <math.h>
#include <stdint.h>

#define BSZ   8
#define C1    256
#define C2    256
#define CM    128
#define Hh    80
#define Ww    80
#define HW    6400
#define N9    9
#define KCN   1152      // CM * 9
#define NOFF  27
#define EPSF  1e-5f

// ---------------- scratch (device globals; no runtime alloc) ----------------
__device__ __align__(16) __half g_yh  [BSZ*HW*CM];    // NHWC y (fp16)
__device__ __align__(16) __half g_zh  [BSZ*HW*CM];    // NHWC z (fp16)
__device__ __align__(16) float  g_pred[BSZ*HW*NOFF];  // per-pixel [27] fp32
__device__ __align__(16) __half g_w1h [CM*C1];        // [o][k]
__device__ __align__(16) __half g_w2h [N9*32*CM];     // [n][o pad 32][c]
__device__ __align__(16) __half g_wdh [N9*CM*CM];     // [n][o][c]
__device__ __align__(16) __half g_w3h [C2*CM];        // [o][k]

__device__ __forceinline__ float silu_f(float v){ return v / (1.f + __expf(-v)); }
__device__ __forceinline__ uint32_t s2u(const void* p){
    return (uint32_t)__cvta_generic_to_shared(p);
}
__device__ __forceinline__ void cpa16(uint32_t s, const void* g){
    asm volatile("cp.async.cg.shared.global [%0], [%1], 16;" :: "r"(s), "l"(g));
}
#define CPA_COMMIT() asm volatile("cp.async.commit_group;" ::: "memory")
#define CPA_WAIT0()  asm volatile("cp.async.wait_group 0;" ::: "memory")

// row pitch in u32: 64 halves data (32 u32) + pad 4 -> 144B rows
#define HPAD 36

#define MMA_F16(accq, a0,a1,a2,a3, b0,b1) \
    asm volatile("mma.sync.aligned.m16n8k16.row.col.f32.f16.f16.f32 " \
        "{%0,%1,%2,%3}, {%4,%5,%6,%7}, {%8,%9}, {%0,%1,%2,%3};" \
        : "+f"((accq)[0]), "+f"((accq)[1]), "+f"((accq)[2]), "+f"((accq)[3]) \
        : "r"(a0), "r"(a1), "r"(a2), "r"(a3), "r"(b0), "r"(b1))

__device__ __forceinline__ void ldsm4(uint32_t* r, uint32_t a){
    asm volatile("ldmatrix.sync.aligned.m8n8.x4.shared.b16 {%0,%1,%2,%3}, [%4];"
        : "=r"(r[0]), "=r"(r[1]), "=r"(r[2]), "=r"(r[3]) : "r"(a));
}

// 64x128 warp-tiled fp16 mma, K-chunk = 64 (k1/k3/k4): warp grid 2m x 4n, acc[2][4][4]
__device__ __forceinline__ void mma_f16_64_k64(uint32_t asu, uint32_t bsu,
        int wm, int wn, int lane, float acc[2][4][4]){
    int l7 = lane & 7;
    uint32_t aBase = asu + (uint32_t)((wm*32 + ((lane>>3)&1)*8 + l7)*HPAD)*4 + (lane>>4)*16;
    uint32_t bBase = bsu + (uint32_t)((wn*32 + ((lane>>4)&1)*8 + l7)*HPAD)*4 + ((lane>>3)&1)*16;
    #pragma unroll
    for (int kk = 0; kk < 4; kk++){
        uint32_t a[2][4];
        #pragma unroll
        for (int mt = 0; mt < 2; mt++)
            ldsm4(a[mt], aBase + (uint32_t)(mt*16*HPAD)*4 + kk*32);
        #pragma unroll
        for (int ntp = 0; ntp < 2; ntp++){
            uint32_t b[4];
            ldsm4(b, bBase + (uint32_t)(ntp*16*HPAD)*4 + kk*32);
            #pragma unroll
            for (int mt = 0; mt < 2; mt++){
                MMA_F16(acc[mt][2*ntp],   a[mt][0],a[mt][1],a[mt][2],a[mt][3], b[0],b[1]);
                MMA_F16(acc[mt][2*ntp+1], a[mt][0],a[mt][1],a[mt][2],a[mt][3], b[2],b[3]);
            }
        }
    }
}

// ---------------- K0: weight conversions/reshapes to fp16 ----------------
__global__ void prep_w(const float* __restrict__ w1, const float* __restrict__ w2,
                       const float* __restrict__ wd, const float* __restrict__ w3){
    int i = blockIdx.x*blockDim.x + threadIdx.x;
    if (i < CM*C1)  g_w1h[i] = __float2half(w1[i]);
    if (i < C2*CM)  g_w3h[i] = __float2half(w3[i]);
    if (i < N9*32*CM){
        int n = i/(32*CM); int o = (i/CM) & 31; int c = i % CM;
        g_w2h[i] = (o < NOFF) ? __float2half(w2[o*KCN + c*9 + n]) : __float2half(0.f);
    }
    if (i < N9*CM*CM){
        int n = i/(CM*CM); int rest = i%(CM*CM); int o = rest/CM, c = rest%CM;
        g_wdh[i] = __float2half(wd[o*KCN + c*9 + n]);
    }
}

// ---------------- K1: conv1x1(256->128) + bn1 + silu -> g_yh, 64px tiles, occ 3 ----------------
__global__ void __launch_bounds__(256, 3) k1_mma(const float* __restrict__ x,
        const float* __restrict__ g1, const float* __restrict__ b1,
        const float* __restrict__ m1, const float* __restrict__ v1){
    __shared__ __align__(16) uint32_t As[64*HPAD];
    __shared__ __align__(16) uint32_t Bs[128*HPAD];
    __shared__ float sS[128], sT[128];
    int blk = blockIdx.x;
    int b_ = blk / 100;
    int p0 = (blk % 100) * 64;
    int tid = threadIdx.x, warp = tid >> 5, lane = tid & 31;
    int wm = warp & 1, wn = warp >> 1, gid = lane >> 2, tig = lane & 3;
    if (tid < 128){
        float s = g1[tid] * rsqrtf(v1[tid] + EPSF);
        sS[tid] = s;
        sT[tid] = b1[tid] - m1[tid]*s;
    }
    float acc[2][4][4] = {};
    const float* xb = x + (size_t)b_*C1*HW + p0;
    uint32_t asu = s2u(As), bsu = s2u(Bs);
    for (int kc = 0; kc < 4; kc++){
        int k0 = kc*64;
        #pragma unroll
        for (int i = 0; i < 4; i++){
            int u = i*256 + tid; int r = u >> 3, seg = u & 7;
            cpa16(bsu + (r*HPAD + seg*4)*4, g_w1h + r*C1 + k0 + seg*8);
        }
        CPA_COMMIT();
        #pragma unroll
        for (int i = 0; i < 8; i++){
            int e = i*256 + tid; int j = e >> 6, px = e & 63;
            float f0 = xb[(size_t)(k0 + 2*j)*HW + px];
            float f1 = xb[(size_t)(k0 + 2*j + 1)*HW + px];
            __half2 hh = __float22half2_rn(make_float2(f0, f1));
            As[px*HPAD + j] = *(uint32_t*)&hh;
        }
        CPA_WAIT0();
        __syncthreads();
        mma_f16_64_k64(asu, bsu, wm, wn, lane, acc);
        __syncthreads();
    }
    #pragma unroll
    for (int mt = 0; mt < 2; mt++){
        int r0 = wm*32 + mt*16 + gid;
        __half2* z0 = (__half2*)(g_yh + (size_t)(b_*HW + p0 + r0)*CM);
        __half2* z1 = (__half2*)(g_yh + (size_t)(b_*HW + p0 + r0 + 8)*CM);
        #pragma unroll
        for (int nt = 0; nt < 4; nt++){
            int cb = wn*32 + nt*8 + 2*tig;
            float s0 = sS[cb], s1 = sS[cb+1], t0 = sT[cb], t1 = sT[cb+1];
            z0[cb>>1] = __float22half2_rn(make_float2(
                silu_f(acc[mt][nt][0]*s0 + t0), silu_f(acc[mt][nt][1]*s1 + t1)));
            z1[cb>>1] = __float22half2_rn(make_float2(
                silu_f(acc[mt][nt][2]*s0 + t0), silu_f(acc[mt][nt][3]*s1 + t1)));
        }
    }
}

// ---------------- K2: conv3x3(128->27), 64px tiles, warp grid 4m x 2n ----------------
__global__ void __launch_bounds__(256, 4) k2_mma(const float* __restrict__ offb){
    __shared__ __align__(16) uint32_t As[64*HPAD];
    __shared__ __align__(16) uint32_t Bs[32*HPAD];
    __shared__ float sB[32];
    int blk = blockIdx.x;
    int b_ = blk / 100;
    int p0 = (blk % 100) * 64;
    int tid = threadIdx.x, warp = tid >> 5, lane = tid & 31;
    int wm = warp & 3, wn2 = warp >> 2;   // 4m x 2n; warp tile 16px x 16o
    int gid = lane >> 2, tig = lane & 3;
    int l7 = lane & 7;
    if (tid < 32) sB[tid] = (tid < NOFF) ? offb[tid] : 0.f;
    uint32_t asu = s2u(As), bsu = s2u(Bs);
    uint32_t aBase = asu + (uint32_t)((wm*16 + ((lane>>3)&1)*8 + l7)*HPAD)*4 + (lane>>4)*16;
    uint32_t bBase = bsu + (uint32_t)((wn2*16 + ((lane>>4)&1)*8 + l7)*HPAD)*4 + ((lane>>3)&1)*16;

    float acc[2][4] = {};
    for (int it = 0; it < 18; it++){
        int n  = it >> 1;
        int c0 = (it & 1) << 6;
        int dy = n/3 - 1, dx = n%3 - 1;
        {   // B: 32 o x 64 ch, 1 cp.async per thread
            int o = tid >> 3, seg = tid & 7;
            cpa16(bsu + (o*HPAD + seg*4)*4, g_w2h + (size_t)n*32*CM + o*CM + c0 + seg*8);
        }
        CPA_COMMIT();
        // A: im2col 16B loads, 2 passes (64px x 8 groups)
        #pragma unroll
        for (int i = 0; i < 2; i++){
            int u = i*256 + tid; int px = u >> 3, grp = u & 7;
            int pg = p0 + px, h = pg / Ww, w = pg % Ww;
            int sy = h + dy, sx = w + dx;
            bool ok = (sy >= 0) & (sy < Hh) & (sx >= 0) & (sx < Ww);
            uint4 t = make_uint4(0u,0u,0u,0u);
            if (ok)
                t = *(const uint4*)(g_yh + (size_t)(b_*HW + sy*Ww + sx)*CM + c0 + grp*8);
            *(uint4*)(As + px*HPAD + grp*4) = t;
        }
        CPA_WAIT0();
        __syncthreads();
        #pragma unroll
        for (int kk = 0; kk < 4; kk++){
            uint32_t a[4];
            ldsm4(a, aBase + kk*32);
            uint32_t b[4];
            ldsm4(b, bBase + kk*32);
            MMA_F16(acc[0], a[0],a[1],a[2],a[3], b[0],b[1]);
            MMA_F16(acc[1], a[0],a[1],a[2],a[3], b[2],b[3]);
        }
        __syncthreads();
    }
    #pragma unroll
    for (int half = 0; half < 2; half++){
        int px = wm*16 + gid + half*8;
        float* pp = g_pred + (size_t)(b_*HW + p0 + px)*NOFF;
        #pragma unroll
        for (int nt = 0; nt < 2; nt++){
            int c = wn2*16 + nt*8 + 2*tig;
            float v0 = acc[nt][half*2 + 0] + sB[c];
            float v1 = acc[nt][half*2 + 1] + sB[c+1];
            if (c >= 18)   v0 = 1.f/(1.f + __expf(-v0));
            if (c+1 >= 18) v1 = 1.f/(1.f + __expf(-v1));
            if (c < NOFF)   pp[c]   = v0;
            if (c+1 < NOFF) pp[c+1] = v1;
        }
    }
}

// ---------------- K3: deform conv, 64px tiles, occ 3, hfma2 gather ----------------
#define K3_F_AS0  0
#define K3_F_AS1  (64*HPAD)
#define K3_F_BS0  (2*64*HPAD)
#define K3_F_BS1  (2*64*HPAD + 128*HPAD)
#define K3_F_IDX  (2*64*HPAD + 2*128*HPAD)
#define K3_F_WTH  (K3_F_IDX + 576)
#define K3_F_S    (K3_F_WTH + 1152)
#define K3_F_T    (K3_F_S + 128)
#define K3_SMEM_F (K3_F_T + 128)

__global__ void __launch_bounds__(256, 3) k3_deform_mma(const float* __restrict__ dcnb,
        const float* __restrict__ g2, const float* __restrict__ b2,
        const float* __restrict__ m2, const float* __restrict__ v2){
    extern __shared__ float sm[];
    uint32_t* AsB[2] = { (uint32_t*)(sm + K3_F_AS0), (uint32_t*)(sm + K3_F_AS1) };
    uint32_t* sIdxP = (uint32_t*)(sm + K3_F_IDX);
    uint2*    sWtH  = (uint2*)(sm + K3_F_WTH);
    float* sS = sm + K3_F_S;
    float* sT = sm + K3_F_T;

    int blk = blockIdx.x;
    int b_ = blk / 100;
    int p0 = (blk % 100) * 64;
    int tid = threadIdx.x, warp = tid >> 5, lane = tid & 31;

    for (int pr = tid; pr < 64*9; pr += 256){
        int p = pr / 9, nn = pr % 9;
        int pg = p0 + p, h = pg / Ww, w = pg % Ww;
        size_t pb = (size_t)(b_*HW + pg) * NOFF;
        float py = (float)(h - 1 + nn/3) + g_pred[pb + 2*nn];
        float qx = (float)(w - 1 + nn%3) + g_pred[pb + 2*nn + 1];
        float mk = g_pred[pb + 18 + nn];
        float y0f = floorf(py), x0f = floorf(qx);
        float wy = py - y0f, wx = qx - x0f;
        int iy0 = (int)y0f, ix0 = (int)x0f, iy1 = iy0 + 1, ix1 = ix0 + 1;
        float vy0 = (iy0 >= 0 && iy0 < Hh) ? 1.f : 0.f;
        float vy1 = (iy1 >= 0 && iy1 < Hh) ? 1.f : 0.f;
        float vx0 = (ix0 >= 0 && ix0 < Ww) ? 1.f : 0.f;
        float vx1 = (ix1 >= 0 && ix1 < Ww) ? 1.f : 0.f;
        int cy0 = min(max(iy0,0),Hh-1), cy1 = min(max(iy1,0),Hh-1);
        int cx0 = min(max(ix0,0),Ww-1), cx1 = min(max(ix1,0),Ww-1);
        uint32_t base = (uint32_t)((b_*HW + cy0*Ww + cx0)*CM);
        uint32_t dxb = (uint32_t)(cx1 - cx0);
        uint32_t dyb = (uint32_t)(cy1 - cy0);
        float w00 = (1.f-wy)*(1.f-wx)*mk*vy0*vx0;
        float w01 = (1.f-wy)*wx      *mk*vy0*vx1;
        float w10 = wy*(1.f-wx)      *mk*vy1*vx0;
        float w11 = wy*wx            *mk*vy1*vx1;
        __half2 h01 = __float22half2_rn(make_float2(w00, w01));
        __half2 h23 = __float22half2_rn(make_float2(w10, w11));
        uint2 wp;
        wp.x = *(uint32_t*)&h01;
        wp.y = *(uint32_t*)&h23;
        sIdxP[pr] = (base << 2) | (dyb << 1) | dxb;
        sWtH[pr]  = wp;
    }
    if (tid < 128){
        float s = g2[tid] * rsqrtf(v2[tid] + EPSF);
        sS[tid] = s;
        sT[tid] = dcnb[tid]*s + b2[tid] - m2[tid]*s;
    }
    __syncthreads();

    int wm = warp & 1, wn = warp >> 1, gid = lane >> 2, tig = lane & 3;
    int sub = lane >> 3, grp = lane & 7;
    float acc[2][4][4] = {};
    uint32_t asuB[2] = { s2u(AsB[0]), s2u(AsB[1]) };
    uint32_t bsuB[2] = { s2u((uint32_t*)(sm + K3_F_BS0)), s2u((uint32_t*)(sm + K3_F_BS1)) };

    auto fillB = [&](int it, int buf){
        int n = it >> 1, c0 = (it & 1) << 6;
        const __half* wn_ = g_wdh + (size_t)n*(CM*CM) + c0;
        uint32_t bu = bsuB[buf];
        #pragma unroll
        for (int i = 0; i < 4; i++){
            int u = i*256 + tid; int o = u >> 3, seg = u & 7;
            cpa16(bu + (o*HPAD + seg*4)*4, wn_ + o*CM + seg*8);
        }
    };
    auto fillA = [&](int it, int buf){
        int n = it >> 1, c0 = (it & 1) << 6;
        const __half* yb = g_yh + c0 + grp*8;
        uint32_t* Ad = AsB[buf];
        #pragma unroll
        for (int p = 0; p < 2; p++){
            int px = warp*8 + p*4 + sub;
            int pr = px*9 + n;
            uint32_t v = sIdxP[pr];
            uint2 wp = sWtH[pr];
            int i00 = (int)(v >> 2);
            int ddx = (int)(v & 1u) * CM;
            int ddy = (int)(v & 2u) * (Ww*CM/2);
            int i01 = i00 + ddx;
            int i10 = i00 + ddy;
            int i11 = i01 + ddy;
            __half2 wpx = *(__half2*)&wp.x;
            __half2 wpy = *(__half2*)&wp.y;
            __half2 w00 = __half2half2(__low2half(wpx));
            __half2 w01 = __half2half2(__high2half(wpx));
            __half2 w10 = __half2half2(__low2half(wpy));
            __half2 w11 = __half2half2(__high2half(wpy));
            uint4 c00 = *(const uint4*)(yb + i00);
            uint4 c01 = *(const uint4*)(yb + i01);
            uint4 c10 = *(const uint4*)(yb + i10);
            uint4 c11 = *(const uint4*)(yb + i11);
            uint4 t;
            #pragma unroll
            for (int q = 0; q < 4; q++){
                __half2 vv = __hmul2(((__half2*)&c00)[q], w00);
                vv = __hfma2(((__half2*)&c01)[q], w01, vv);
                vv = __hfma2(((__half2*)&c10)[q], w10, vv);
                vv = __hfma2(((__half2*)&c11)[q], w11, vv);
                ((__half2*)&t)[q] = vv;
            }
            *(uint4*)(Ad + px*HPAD + grp*4) = t;
        }
    };

    fillB(0, 0); CPA_COMMIT();
    fillA(0, 0);
    CPA_WAIT0();
    __syncthreads();

    int cur = 0;
    for (int it = 0; it < 18; it++){
        int nb = cur ^ 1;
        if (it < 17){ fillB(it+1, nb); CPA_COMMIT(); }
        mma_f16_64_k64(asuB[cur], bsuB[cur], wm, wn, lane, acc);
        if (it < 17) fillA(it+1, nb);
        CPA_WAIT0();
        __syncthreads();
        cur = nb;
    }

    #pragma unroll
    for (int mt = 0; mt < 2; mt++){
        int r0 = wm*32 + mt*16 + gid;
        __half2* z0 = (__half2*)(g_zh + (size_t)(b_*HW + p0 + r0)*CM);
        __half2* z1 = (__half2*)(g_zh + (size_t)(b_*HW + p0 + r0 + 8)*CM);
        #pragma unroll
        for (int nt = 0; nt < 4; nt++){
            int cb = wn*32 + nt*8 + 2*tig;
            float s0 = sS[cb], s1 = sS[cb+1], t0 = sT[cb], t1 = sT[cb+1];
            z0[cb>>1] = __float22half2_rn(make_float2(
                silu_f(acc[mt][nt][0]*s0 + t0), silu_f(acc[mt][nt][1]*s1 + t1)));
            z1[cb>>1] = __float22half2_rn(make_float2(
                silu_f(acc[mt][nt][2]*s0 + t0), silu_f(acc[mt][nt][3]*s1 + t1)));
        }
    }
}

// ---------------- K4: conv1x1(128->256) + bn3 + silu + residual, 64px tiles, occ 3 ----------------
__global__ void __launch_bounds__(256, 3) k4_mma(const float* __restrict__ x, float* __restrict__ out,
        const float* __restrict__ g3, const float* __restrict__ b3,
        const float* __restrict__ m3, const float* __restrict__ v3){
    __shared__ __align__(16) uint32_t As[64*HPAD];
    __shared__ __align__(16) uint32_t Bs[128*HPAD];
    __shared__ float sS[128], sT[128];
    int blk = blockIdx.x;
    int b_ = blk / 100;
    int p0 = (blk % 100) * 64;
    int o0g = blockIdx.y * 128;
    int tid = threadIdx.x, warp = tid >> 5, lane = tid & 31;
    int wm = warp & 1, wn = warp >> 1, gid = lane >> 2, tig = lane & 3;
    if (tid < 128){
        int o = o0g + tid;
        float s = g3[o] * rsqrtf(v3[o] + EPSF);
        sS[tid] = s;
        sT[tid] = b3[o] - m3[o]*s;
    }
    float acc[2][4][4] = {};
    const __half* zt = g_zh + (size_t)(b_*HW + p0)*CM;
    const __half* wb = g_w3h + (size_t)o0g*CM;
    uint32_t asu = s2u(As), bsu = s2u(Bs);
    for (int kc = 0; kc < 2; kc++){
        int k0 = kc*64;
        #pragma unroll
        for (int i = 0; i < 2; i++){
            int u = i*256 + tid; int r = u >> 3, seg = u & 7;
            cpa16(asu + (r*HPAD + seg*4)*4, zt + (size_t)r*CM + k0 + seg*8);
        }
        #pragma unroll
        for (int i = 0; i < 4; i++){
            int u = i*256 + tid; int r = u >> 3, seg = u & 7;
            cpa16(bsu + (r*HPAD + seg*4)*4, wb + r*CM + k0 + seg*8);
        }
        CPA_COMMIT();
        CPA_WAIT0();
        __syncthreads();
        mma_f16_64_k64(asu, bsu, wm, wn, lane, acc);
        __syncthreads();
    }
    #pragma unroll
    for (int mt = 0; mt < 2; mt++){
        int pg0 = p0 + wm*32 + mt*16 + gid;
        #pragma unroll
        for (int nt = 0; nt < 4; nt++){
            int o = o0g + wn*32 + nt*8 + 2*tig;
            float s0 = sS[o - o0g], s1 = sS[o - o0g + 1];
            float t0 = sT[o - o0g], t1 = sT[o - o0g + 1];
            size_t i00 = ((size_t)b_*C2 + o)*HW + pg0;
            size_t i01 = i00 + HW;
            out[i00]     = x[i00]     + silu_f(acc[mt][nt][0]*s0 + t0);
            out[i01]     = x[i01]     + silu_f(acc[mt][nt][1]*s1 + t1);
            out[i00 + 8] = x[i00 + 8] + silu_f(acc[mt][nt][2]*s0 + t0);
            out[i01 + 8] = x[i01 + 8] + silu_f(acc[mt][nt][3]*s1 + t1);
        }
    }
}

// ---------------- launch ----------------
extern "C" void kernel_launch(void* const* d_in, const int* in_sizes, int n_in,
                              void* d_out, int out_size){
    const float* x     = (const float*)d_in[0];
    const float* cv1_w = (const float*)d_in[1];
    const float* bn1g  = (const float*)d_in[2];
    const float* bn1b  = (const float*)d_in[3];
    const float* bn1m  = (const float*)d_in[4];
    const float* bn1v  = (const float*)d_in[5];
    const float* off_w = (const float*)d_in[6];
    const float* off_b = (const float*)d_in[7];
    const float* dcn_w = (const float*)d_in[8];
    const float* dcn_b = (const float*)d_in[9];
    const float* bn2g  = (const float*)d_in[10];
    const float* bn2b  = (const float*)d_in[11];
    const float* bn2m  = (const float*)d_in[12];
    const float* bn2v  = (const float*)d_in[13];
    const float* cv3_w = (const float*)d_in[14];
    const float* bn3g  = (const float*)d_in[15];
    const float* bn3b  = (const float*)d_in[16];
    const float* bn3m  = (const float*)d_in[17];
    const float* bn3v  = (const float*)d_in[18];
    float* out = (float*)d_out;

    prep_w<<<(N9*CM*CM + 255)/256, 256>>>(cv1_w, off_w, dcn_w, cv3_w);
    k1_mma<<<BSZ*100, 256>>>(x, bn1g, bn1b, bn1m, bn1v);
    k2_mma<<<BSZ*100, 256>>>(off_b);

    int smem_bytes = K3_SMEM_F * 4;  // 63232 B
    cudaFuncSetAttribute(k3_deform_mma, cudaFuncAttributeMaxDynamicSharedMemorySize, smem_bytes);
    k3_deform_mma<<<BSZ*100, 256, smem_bytes>>>(dcn_b, bn2g, bn2b, bn2m, bn2v);

    k4_mma<<<dim3(BSZ*100, 2), 256>>>(x, out, bn3g, bn3b, bn3m, bn3v);
}